// round 9
// baseline (speedup 1.0000x reference)
#include <cuda_runtime.h>
#include <cuda_bf16.h>
#include <cstdint>

#define NN 4096
#define BB 512
#define DTc 0.1f

#define BM 128
#define BN 128
#define BKt 32
#define NCHUNK 128                   // K-chunks per tile
#define NTILES 128                   // 32 M x 4 N
#define TOTC (NTILES * NCHUNK)       // 16384
#define UNITC 16                     // chunks per claim (divides NCHUNK)
#define ROWB 80
#define TILEB (128 * ROWB)
#define STAGEB (4 * TILEB)           // 40960
#define NSTG 4
#define CST_OFF (NSTG * STAGEB)      // 163840
#define SMEM_BYTES (CST_OFF + 128 * 132 * 4)   // 231424
#define NSLOT 8

// --------------------------------------------------------------------------
__device__ __align__(256) __nv_bfloat16 g_Ahi[(size_t)NN * NN];    // 32 MB
__device__ __align__(256) __nv_bfloat16 g_Alo[(size_t)NN * NN];    // 32 MB
__device__ __align__(256) __nv_bfloat16 g_Bhi[2][(size_t)BB * NN]; // 2x4 MB
__device__ __align__(256) __nv_bfloat16 g_Blo[2][(size_t)BB * NN]; // 2x4 MB
__device__ __align__(256) float g_Cpart[(size_t)NTILES * NSLOT * 128 * 128]; // 64 MB
__device__ int g_cnt[NTILES];
__device__ int g_slotc[NTILES];
__device__ unsigned int g_cursor[2];
__device__ float g_x[2][2 * BB];
__device__ float g_zha[2][BB];

// --------------------------------------------------------------------------
__device__ __forceinline__ uint32_t smem_u32(const void* p) {
    return (uint32_t)__cvta_generic_to_shared((void*)p);
}
__device__ __forceinline__ void cp16(uint32_t dst, const void* src) {
    asm volatile("cp.async.cg.shared.global [%0], [%1], 16;" :: "r"(dst), "l"(src) : "memory");
}
__device__ __forceinline__ void ldsm4(uint32_t* r, uint32_t a) {
    asm volatile("ldmatrix.sync.aligned.m8n8.x4.shared.b16 {%0,%1,%2,%3}, [%4];"
                 : "=r"(r[0]), "=r"(r[1]), "=r"(r[2]), "=r"(r[3]) : "r"(a));
}
__device__ __forceinline__ void ldsm2(uint32_t* r, uint32_t a) {
    asm volatile("ldmatrix.sync.aligned.m8n8.x2.shared.b16 {%0,%1}, [%2];"
                 : "=r"(r[0]), "=r"(r[1]) : "r"(a));
}
__device__ __forceinline__ void mma_bf16(float* d, const uint32_t* a, const uint32_t* b) {
    asm("mma.sync.aligned.m16n8k16.row.col.f32.bf16.bf16.f32 "
        "{%0,%1,%2,%3}, {%4,%5,%6,%7}, {%8,%9}, {%0,%1,%2,%3};"
        : "+f"(d[0]), "+f"(d[1]), "+f"(d[2]), "+f"(d[3])
        : "r"(a[0]), "r"(a[1]), "r"(a[2]), "r"(a[3]), "r"(b[0]), "r"(b[1]));
}

// --------------------------------------------------------------------------
// Build A_hi/A_lo (bf16 split of P22); zero counters.
// --------------------------------------------------------------------------
__global__ void build_split_kernel(const float* __restrict__ W,
                                   const float* __restrict__ U,
                                   const float* __restrict__ V,
                                   const float* __restrict__ Mv,
                                   const float* __restrict__ Z,
                                   const float* __restrict__ Cc,
                                   const float* __restrict__ Bm) {
    if (blockIdx.x == 0 && blockIdx.y == 0) {
        int tIdx = threadIdx.x;
        g_zha[0][tIdx] = 0.f;       g_zha[1][tIdx] = 0.f;
        g_zha[0][tIdx + 256] = 0.f; g_zha[1][tIdx + 256] = 0.f;
        if (tIdx < NTILES) { g_cnt[tIdx] = 0; g_slotc[tIdx] = 0; }
        if (tIdx < 2) g_cursor[tIdx] = 0;
    }
    int i = blockIdx.y;
    int j = (blockIdx.x * blockDim.x + threadIdx.x) * 4;
    float cb = Cc[0] * Bm[0] + Cc[1] * Bm[1];
    float mi = Mv[i];
    float u0 = U[i * 4 + 0], u1 = U[i * 4 + 1], u2 = U[i * 4 + 2], u3 = U[i * 4 + 3];
    float4 w = *(const float4*)(W + (size_t)i * NN + j);
    const float* wp = &w.x;
    union { __nv_bfloat16 h[4]; uint2 u; } ph, pl;
#pragma unroll
    for (int jj = 0; jj < 4; ++jj) {
        int jc = j + jj;
        float4 vv = *(const float4*)(V + (size_t)jc * 4);
        float uv = u0 * vv.x + u1 * vv.y + u2 * vv.z + u3 * vv.w;
        float val = DTc * (wp[jj] + uv) + cb * mi * Z[jc];
        if (jc == i) val += 1.0f - DTc;
        __nv_bfloat16 hi = __float2bfloat16(val);
        ph.h[jj] = hi;
        pl.h[jj] = __float2bfloat16(val - __bfloat162float(hi));
    }
    *(uint2*)(g_Ahi + (size_t)i * NN + j) = ph.u;
    *(uint2*)(g_Alo + (size_t)i * NN + j) = pl.u;
}

// --------------------------------------------------------------------------
// init_all: h0 -> traj_0 h-block + transposed bf16 split + zh0 + x init
// --------------------------------------------------------------------------
__global__ void init_all_kernel(const float* __restrict__ h0,
                                const float* __restrict__ x0,
                                const float* __restrict__ x1,
                                const float* __restrict__ Z,
                                float* __restrict__ traj0h) {
    __shared__ float t[32][33];
    __shared__ float zs[8][33];
    int m0 = blockIdx.x * 32, b0 = blockIdx.y * 32;
    int tx = threadIdx.x, ty = threadIdx.y;
    if (blockIdx.x == 0 && blockIdx.y == 0) {
        int tid = ty * 32 + tx;
#pragma unroll
        for (int it = 0; it < 2; ++it) {
            int b = tid + it * 256;
            g_x[0][b] = x0[b];
            g_x[0][BB + b] = x1[b];
        }
    }
#pragma unroll
    for (int j = 0; j < 32; j += 8) {
        size_t a = (size_t)(m0 + ty + j) * BB + b0 + tx;
        float v = h0[a];
        traj0h[a] = v;
        t[ty + j][tx] = v;
    }
    __syncthreads();
    {
        float s = 0.f;
#pragma unroll
        for (int i = 0; i < 4; ++i) {
            int r = ty * 4 + i;
            s = fmaf(Z[m0 + r], t[r][tx], s);
        }
        zs[ty][tx] = s;
    }
#pragma unroll
    for (int j = 0; j < 32; j += 8) {
        float v = t[tx][ty + j];
        size_t o = (size_t)(b0 + ty + j) * NN + m0 + tx;
        __nv_bfloat16 hi = __float2bfloat16(v);
        g_Bhi[0][o] = hi;
        g_Blo[0][o] = __float2bfloat16(v - __bfloat162float(hi));
    }
    __syncthreads();
    if (ty == 0) {
        float s = 0.f;
#pragma unroll
        for (int r = 0; r < 8; ++r) s += zs[r][tx];
        atomicAdd(&g_zha[0][b0 + tx], s);
    }
}

// --------------------------------------------------------------------------
// Load one K-chunk (32k) of chunk id c into stage 'stg' (bases derived from c).
// --------------------------------------------------------------------------
__device__ __forceinline__ void load_chunk(uint32_t stg, int c, int tid,
                                           const __nv_bfloat16* Ah, const __nv_bfloat16* Al,
                                           const __nv_bfloat16* Bh, const __nv_bfloat16* Bl) {
    int t = c >> 7;
    int kt = c & 127;
    int rowBase = (t >> 2) * BM;
    int colBase = (t & 3) * BN;
#pragma unroll
    for (int i = 0; i < 8; ++i) {
        int ch = i * 256 + tid;
        int tile = ch >> 9;
        int r = (ch >> 2) & 127;
        int cc = ch & 3;
        const __nv_bfloat16* base = (tile == 0) ? Ah : (tile == 1) ? Al : (tile == 2) ? Bh : Bl;
        int rb = (tile < 2) ? rowBase : colBase;
        const char* src = (const char*)base + ((size_t)(rb + r) * NN + kt * BKt + cc * 8) * 2;
        uint32_t dst = stg + tile * TILEB + r * ROWB + cc * 16;
        cp16(dst, src);
    }
}

// --------------------------------------------------------------------------
// Work-stealing stream-K fused step kernel. grid = nsm, block 256.
// --------------------------------------------------------------------------
__global__ void __launch_bounds__(256, 1) gemm_sk_kernel(
    int p, int do_mma,
    const float* __restrict__ Mv,
    const float* __restrict__ Cc, const float* __restrict__ Amat,
    const float* __restrict__ Bm, const float* __restrict__ Z,
    float* __restrict__ trajh_next,
    float* __restrict__ trajx_cur,
    float* __restrict__ con_cur) {
    extern __shared__ __align__(128) char smem[];
    __shared__ int sClaim, sSlot, sFin;
    uint32_t sb = smem_u32(smem);
    float* Cst = (float*)(smem + CST_OFF);
    int tid = threadIdx.x;
    int lane = tid & 31;
    int wid = tid >> 5;
    int q2 = p ^ 1;

    // ---- fused x-update (step t) + next-step cursor reset, CTA 0 only ----
    if (blockIdx.x == 0) {
#pragma unroll
        for (int it = 0; it < 2; ++it) {
            int b = tid + it * 256;
            float zh = g_zha[p][b];
            g_zha[p][b] = 0.f;
            float xv0 = g_x[p][b], xv1 = g_x[p][BB + b];
            con_cur[b] = Bm[1] * zh;
            trajx_cur[b] = xv0;
            trajx_cur[BB + b] = xv1;
            g_x[q2][b] = Amat[0] * xv0 + Amat[1] * xv1 + Bm[0] * zh;
            g_x[q2][BB + b] = Amat[2] * xv0 + Amat[3] * xv1 + Bm[1] * zh;
        }
        if (tid == 0) g_cursor[q2] = 0;
    }
    if (!do_mma) return;

    const __nv_bfloat16* Ah = g_Ahi;
    const __nv_bfloat16* Al = g_Alo;
    const __nv_bfloat16* Bh = g_Bhi[p];
    const __nv_bfloat16* Bl = g_Blo[p];

    int mb = (wid >> 2) * 64;
    int nb = (wid & 3) * 32;
    uint32_t aRow = (uint32_t)(mb + (lane & 15));
    uint32_t aK = (uint32_t)((lane >> 4) * 8);
    uint32_t bRow = (uint32_t)(nb + (lane & 7));
    uint32_t bK = (uint32_t)(((lane >> 3) & 1) * 8);

    float CA0 = Cc[0] * Amat[0] + Cc[1] * Amat[2];
    float CA1 = Cc[0] * Amat[1] + Cc[1] * Amat[3];

    // ---- claim first two units ----
    if (tid == 0) sClaim = (int)atomicAdd(&g_cursor[p], UNITC);
    __syncthreads();
    int q0 = sClaim;
    __syncthreads();
    if (tid == 0) sClaim = (int)atomicAdd(&g_cursor[p], UNITC);
    __syncthreads();
    int q1 = sClaim;

    if (q0 >= TOTC) return;

    // prologue: stages 0..NSTG-1 = chunks q0+0..q0+3 (NSTG < UNITC)
#pragma unroll
    for (int s = 0; s < NSTG; ++s) {
        load_chunk(sb + s * STAGEB, q0 + s, tid, Ah, Al, Bh, Bl);
        asm volatile("cp.async.commit_group;" ::: "memory");
    }

    float acc[4][4][4];
#pragma unroll
    for (int mi = 0; mi < 4; ++mi)
#pragma unroll
        for (int ni = 0; ni < 4; ++ni)
#pragma unroll
            for (int k = 0; k < 4; ++k) acc[mi][ni][k] = 0.f;

    int sidx = 0, mPos = 0;
    int accTile = q0 >> 7;
    int segChunks = 0;

    for (;;) {
        // ---- consume one chunk from stage sidx ----
        asm volatile("cp.async.wait_group %0;" :: "n"(NSTG - 1) : "memory");
        __syncthreads();
        uint32_t stg = sb + (uint32_t)sidx * STAGEB;
#pragma unroll
        for (int ks = 0; ks < BKt; ks += 16) {
            uint32_t ah[4][4], al2[4][4], bh2[4][2], bl2[4][2];
#pragma unroll
            for (int mi = 0; mi < 4; ++mi) {
                uint32_t a = stg + (aRow + mi * 16) * ROWB + (aK + ks) * 2;
                ldsm4(ah[mi], a);
                ldsm4(al2[mi], a + TILEB);
            }
#pragma unroll
            for (int ni = 0; ni < 4; ++ni) {
                uint32_t a = stg + 2 * TILEB + (bRow + ni * 8) * ROWB + (bK + ks) * 2;
                ldsm2(bh2[ni], a);
                ldsm2(bl2[ni], a + TILEB);
            }
#pragma unroll
            for (int mi = 0; mi < 4; ++mi)
#pragma unroll
                for (int ni = 0; ni < 4; ++ni) {
                    mma_bf16(acc[mi][ni], ah[mi], bh2[ni]);
                    mma_bf16(acc[mi][ni], ah[mi], bl2[ni]);
                    mma_bf16(acc[mi][ni], al2[mi], bh2[ni]);
                }
        }
        __syncthreads();

        // ---- load ahead (stream position mPos+NSTG) into the freed stage ----
        {
            int lpos = mPos + NSTG;
            int lc; bool lv;
            if (lpos < UNITC) { lc = q0 + lpos; lv = (q0 < TOTC); }
            else              { lc = q1 + (lpos - UNITC); lv = (q1 < TOTC); }
            if (lv) load_chunk(stg, lc, tid, Ah, Al, Bh, Bl);
            asm volatile("cp.async.commit_group;" ::: "memory");
        }
        sidx = (sidx + 1) & (NSTG - 1);
        ++mPos;
        ++segChunks;

        int nTile = accTile;
        if (mPos == UNITC) {
            q0 = q1;
            __syncthreads();
            if (tid == 0) sClaim = (int)atomicAdd(&g_cursor[p], UNITC);
            __syncthreads();
            q1 = sClaim;
            mPos = 0;
            nTile = (q0 < TOTC) ? (q0 >> 7) : -1;
        }

        if (nTile != accTile) {
            // ================= segment boundary: finalize accTile =========
            int tile = accTile;
            int rowB = (tile >> 2) * BM;
            int colB = (tile & 3) * BN;

            // pass 1: frags -> Cst [n][132]
#pragma unroll
            for (int mi = 0; mi < 4; ++mi)
#pragma unroll
                for (int ni = 0; ni < 4; ++ni) {
                    int m = mb + mi * 16 + (lane >> 2);
                    int n = nb + ni * 8 + (lane & 3) * 2;
                    Cst[n * 132 + m] = acc[mi][ni][0];
                    Cst[(n + 1) * 132 + m] = acc[mi][ni][1];
                    Cst[n * 132 + m + 8] = acc[mi][ni][2];
                    Cst[(n + 1) * 132 + m + 8] = acc[mi][ni][3];
                }
            __syncthreads();

            if (tid == 0) sSlot = atomicAdd(&g_slotc[tile], 1);
            __syncthreads();
            int slot = sSlot;
            float* part = g_Cpart + ((size_t)(tile * NSLOT + slot) << 14);
#pragma unroll
            for (int it = 0; it < 16; ++it) {
                int lin = it * 1024 + tid * 4;
                int n = lin >> 7, m = lin & 127;
                *(float4*)&part[lin] = *(float4*)&Cst[n * 132 + m];
            }
            __threadfence();
            __syncthreads();
            if (tid == 0) {
                int old = atomicAdd(&g_cnt[tile], segChunks);
                sFin = (old + segChunks == NCHUNK) ? 1 : 0;
            }
            __syncthreads();

            if (sFin) {
                __threadfence();
                int nslots = g_slotc[tile];
                for (int s = 0; s < nslots; ++s) {
                    if (s == slot) continue;
                    const float* op = g_Cpart + ((size_t)(tile * NSLOT + s) << 14);
#pragma unroll
                    for (int it = 0; it < 16; ++it) {
                        int lin = it * 1024 + tid * 4;
                        int n = lin >> 7, m = lin & 127;
                        float4 a = *(float4*)&Cst[n * 132 + m];
                        float4 b = *(const float4*)&op[lin];
                        a.x += b.x; a.y += b.y; a.z += b.z; a.w += b.w;
                        *(float4*)&Cst[n * 132 + m] = a;
                    }
                }
                __syncthreads();

                // pass 2 (n-major): P21 term; Bhi/Blo out; zh partial
                {
                    int n = tid >> 1;
                    int m0 = (tid & 1) * 64;
                    float e = CA0 * g_x[p][colB + n] + CA1 * g_x[p][BB + colB + n];
                    __nv_bfloat16* __restrict__ Bhn = g_Bhi[q2];
                    __nv_bfloat16* __restrict__ Bln = g_Blo[q2];
                    size_t obase = (size_t)(colB + n) * NN + rowB;
                    float zp = 0.f;
#pragma unroll
                    for (int q = 0; q < 16; ++q) {
                        int m = m0 + q * 4;
                        float4 c = *(float4*)&Cst[n * 132 + m];
                        float4 mv4 = *(const float4*)&Mv[rowB + m];
                        float4 z4 = *(const float4*)&Z[rowB + m];
                        float4 v;
                        v.x = c.x + DTc * mv4.x * e;
                        v.y = c.y + DTc * mv4.y * e;
                        v.z = c.z + DTc * mv4.z * e;
                        v.w = c.w + DTc * mv4.w * e;
                        *(float4*)&Cst[n * 132 + m] = v;
                        zp += z4.x * v.x + z4.y * v.y + z4.z * v.z + z4.w * v.w;
                        union { __nv_bfloat16 h[4]; uint2 u; } ph, pl;
                        const float* vp = &v.x;
#pragma unroll
                        for (int j = 0; j < 4; ++j) {
                            __nv_bfloat16 hi = __float2bfloat16(vp[j]);
                            ph.h[j] = hi;
                            pl.h[j] = __float2bfloat16(vp[j] - __bfloat162float(hi));
                        }
                        *(uint2*)&Bhn[obase + m] = ph.u;
                        *(uint2*)&Bln[obase + m] = pl.u;
                    }
                    zp += __shfl_xor_sync(0xFFFFFFFFu, zp, 1);
                    if ((tid & 1) == 0)
                        atomicAdd(&g_zha[q2][colB + n], zp);
                }
                __syncthreads();

                // pass 3 (m-major): traj_{t+1} h-block
                {
                    int m = tid >> 1;
                    int n0 = (tid & 1) * 64;
                    size_t tb = (size_t)(rowB + m) * BB + colB + n0;
#pragma unroll
                    for (int q = 0; q < 16; ++q) {
                        float4 v;
                        v.x = Cst[(n0 + q * 4 + 0) * 132 + m];
                        v.y = Cst[(n0 + q * 4 + 1) * 132 + m];
                        v.z = Cst[(n0 + q * 4 + 2) * 132 + m];
                        v.w = Cst[(n0 + q * 4 + 3) * 132 + m];
                        *(float4*)&trajh_next[tb + q * 4] = v;
                    }
                }
                if (tid == 0) { g_cnt[tile] = 0; g_slotc[tile] = 0; }
            }
            __syncthreads();

            // reset accs for next segment
#pragma unroll
            for (int mi = 0; mi < 4; ++mi)
#pragma unroll
                for (int ni = 0; ni < 4; ++ni)
#pragma unroll
                    for (int k = 0; k < 4; ++k) acc[mi][ni][k] = 0.f;
            segChunks = 0;
            accTile = nTile;
            if (nTile < 0) break;
        }
    }
}

// --------------------------------------------------------------------------
extern "C" void kernel_launch(void* const* d_in, const int* in_sizes, int n_in,
                              void* d_out, int out_size) {
    const float* x0 = (const float*)d_in[0];
    const float* x1 = (const float*)d_in[1];
    const float* h0 = (const float*)d_in[2];
    const float* A  = (const float*)d_in[3];
    const float* Bm = (const float*)d_in[4];
    const float* C  = (const float*)d_in[5];
    const float* Mv = (const float*)d_in[6];
    const float* Z  = (const float*)d_in[7];
    const float* U  = (const float*)d_in[8];
    const float* V  = (const float*)d_in[9];
    const float* W  = (const float*)d_in[10];

    long long per_step_full = (long long)BB * (NN + 2 + 1);
    int steps = (int)((long long)out_size / per_step_full);
    if ((long long)steps * per_step_full != (long long)out_size)
        steps = (int)((long long)out_size / ((long long)BB * (NN + 2)));

    float* out  = (float*)d_out;
    float* traj = out;
    float* con  = out + (size_t)steps * (NN + 2) * BB;

    int nsm = 0;
    cudaDeviceGetAttribute(&nsm, cudaDevAttrMultiProcessorCount, 0);
    if (nsm < 8 || nsm > 512) nsm = 148;

    cudaFuncSetAttribute(gemm_sk_kernel,
                         cudaFuncAttributeMaxDynamicSharedMemorySize, SMEM_BYTES);

    build_split_kernel<<<dim3(NN / 4 / 256, NN), 256>>>(W, U, V, Mv, Z, C, Bm);
    init_all_kernel<<<dim3(NN / 32, BB / 32), dim3(32, 8)>>>(h0, x0, x1, Z, traj + 2 * BB);

    for (int t = 0; t < steps; ++t) {
        int p = t & 1;
        int do_mma = (t < steps - 1);
        float* traj_t = traj + (size_t)t * (NN + 2) * BB;
        float* trajh_next = traj + (size_t)(t + 1) * (NN + 2) * BB + 2 * BB;
        if (!do_mma) trajh_next = traj_t + 2 * BB;   // unused, keep in-bounds
        gemm_sk_kernel<<<nsm, 256, SMEM_BYTES>>>(
            p, do_mma, Mv, C, A, Bm, Z,
            trajh_next, traj_t, con + (size_t)t * BB);
    }
}

// round 10
// speedup vs baseline: 1.4241x; 1.4241x over previous
#include <cuda_runtime.h>
#include <cuda_bf16.h>
#include <cstdint>

#define NN 4096
#define BB 512
#define DTc 0.1f

// GEMM tiling (mma.sync bf16)
#define BM 128
#define BN 128
#define BKt 32
#define NCHUNK 128                   // K-chunks per tile (4096/32)
#define NTILES 128                   // 32 M x 4 N
#define TOTC (NTILES * NCHUNK)       // 16384
#define ROWB 80
#define TILEB (128 * ROWB)
#define STAGEB (4 * TILEB)           // 40960
#define NSTG 4
#define CST_OFF (NSTG * STAGEB)      // 163840
#define SMEM_BYTES (CST_OFF + 128 * 132 * 4)   // 231424

// --------------------------------------------------------------------------
__device__ __align__(256) __nv_bfloat16 g_Ahi[(size_t)NN * NN];    // 32 MB
__device__ __align__(256) __nv_bfloat16 g_Alo[(size_t)NN * NN];    // 32 MB
__device__ __align__(256) __nv_bfloat16 g_Bhi[2][(size_t)BB * NN]; // 2x4 MB
__device__ __align__(256) __nv_bfloat16 g_Blo[2][(size_t)BB * NN]; // 2x4 MB
__device__ __align__(256) float g_Cpart[(size_t)NTILES * 3 * 128 * 128]; // 25.2 MB
__device__ int g_cnt[NTILES];        // zero-init; kernel restores zeros
__device__ float g_x[2][2 * BB];
__device__ float g_zha[2][BB];

// --------------------------------------------------------------------------
__device__ __forceinline__ uint32_t smem_u32(const void* p) {
    return (uint32_t)__cvta_generic_to_shared((void*)p);
}
__device__ __forceinline__ void cp16(uint32_t dst, const void* src) {
    asm volatile("cp.async.cg.shared.global [%0], [%1], 16;" :: "r"(dst), "l"(src) : "memory");
}
__device__ __forceinline__ void ldsm4(uint32_t* r, uint32_t a) {
    asm volatile("ldmatrix.sync.aligned.m8n8.x4.shared.b16 {%0,%1,%2,%3}, [%4];"
                 : "=r"(r[0]), "=r"(r[1]), "=r"(r[2]), "=r"(r[3]) : "r"(a));
}
__device__ __forceinline__ void ldsm2(uint32_t* r, uint32_t a) {
    asm volatile("ldmatrix.sync.aligned.m8n8.x2.shared.b16 {%0,%1}, [%2];"
                 : "=r"(r[0]), "=r"(r[1]) : "r"(a));
}
__device__ __forceinline__ void mma_bf16(float* d, const uint32_t* a, const uint32_t* b) {
    asm("mma.sync.aligned.m16n8k16.row.col.f32.bf16.bf16.f32 "
        "{%0,%1,%2,%3}, {%4,%5,%6,%7}, {%8,%9}, {%0,%1,%2,%3};"
        : "+f"(d[0]), "+f"(d[1]), "+f"(d[2]), "+f"(d[3])
        : "r"(a[0]), "r"(a[1]), "r"(a[2]), "r"(a[3]), "r"(b[0]), "r"(b[1]));
}

// --------------------------------------------------------------------------
// Build A_hi/A_lo (bf16 split of P22); zero zh accumulators + counters.
// --------------------------------------------------------------------------
__global__ void build_split_kernel(const float* __restrict__ W,
                                   const float* __restrict__ U,
                                   const float* __restrict__ V,
                                   const float* __restrict__ Mv,
                                   const float* __restrict__ Z,
                                   const float* __restrict__ Cc,
                                   const float* __restrict__ Bm) {
    if (blockIdx.x == 0 && blockIdx.y == 0) {
        int tIdx = threadIdx.x;
        g_zha[0][tIdx] = 0.f;       g_zha[1][tIdx] = 0.f;
        g_zha[0][tIdx + 256] = 0.f; g_zha[1][tIdx + 256] = 0.f;
        if (tIdx < NTILES) g_cnt[tIdx] = 0;
    }
    int i = blockIdx.y;
    int j = (blockIdx.x * blockDim.x + threadIdx.x) * 4;
    float cb = Cc[0] * Bm[0] + Cc[1] * Bm[1];
    float mi = Mv[i];
    float u0 = U[i * 4 + 0], u1 = U[i * 4 + 1], u2 = U[i * 4 + 2], u3 = U[i * 4 + 3];
    float4 w = *(const float4*)(W + (size_t)i * NN + j);
    const float* wp = &w.x;
    union { __nv_bfloat16 h[4]; uint2 u; } ph, pl;
#pragma unroll
    for (int jj = 0; jj < 4; ++jj) {
        int jc = j + jj;
        float4 vv = *(const float4*)(V + (size_t)jc * 4);
        float uv = u0 * vv.x + u1 * vv.y + u2 * vv.z + u3 * vv.w;
        float val = DTc * (wp[jj] + uv) + cb * mi * Z[jc];
        if (jc == i) val += 1.0f - DTc;
        __nv_bfloat16 hi = __float2bfloat16(val);
        ph.h[jj] = hi;
        pl.h[jj] = __float2bfloat16(val - __bfloat162float(hi));
    }
    *(uint2*)(g_Ahi + (size_t)i * NN + j) = ph.u;
    *(uint2*)(g_Alo + (size_t)i * NN + j) = pl.u;
}

// --------------------------------------------------------------------------
// init_all: h0 -> traj_0 h-block + transposed bf16 split + zh0 + x init
// --------------------------------------------------------------------------
__global__ void init_all_kernel(const float* __restrict__ h0,
                                const float* __restrict__ x0,
                                const float* __restrict__ x1,
                                const float* __restrict__ Z,
                                float* __restrict__ traj0h) {
    __shared__ float t[32][33];
    __shared__ float zs[8][33];
    int m0 = blockIdx.x * 32, b0 = blockIdx.y * 32;
    int tx = threadIdx.x, ty = threadIdx.y;
    if (blockIdx.x == 0 && blockIdx.y == 0) {
        int tid = ty * 32 + tx;
#pragma unroll
        for (int it = 0; it < 2; ++it) {
            int b = tid + it * 256;
            g_x[0][b] = x0[b];
            g_x[0][BB + b] = x1[b];
        }
    }
#pragma unroll
    for (int j = 0; j < 32; j += 8) {
        size_t a = (size_t)(m0 + ty + j) * BB + b0 + tx;
        float v = h0[a];
        traj0h[a] = v;
        t[ty + j][tx] = v;
    }
    __syncthreads();
    {
        float s = 0.f;
#pragma unroll
        for (int i = 0; i < 4; ++i) {
            int r = ty * 4 + i;
            s = fmaf(Z[m0 + r], t[r][tx], s);
        }
        zs[ty][tx] = s;
    }
#pragma unroll
    for (int j = 0; j < 32; j += 8) {
        float v = t[tx][ty + j];
        size_t o = (size_t)(b0 + ty + j) * NN + m0 + tx;
        __nv_bfloat16 hi = __float2bfloat16(v);
        g_Bhi[0][o] = hi;
        g_Blo[0][o] = __float2bfloat16(v - __bfloat162float(hi));
    }
    __syncthreads();
    if (ty == 0) {
        float s = 0.f;
#pragma unroll
        for (int r = 0; r < 8; ++r) s += zs[r][tx];
        atomicAdd(&g_zha[0][b0 + tx], s);
    }
}

// --------------------------------------------------------------------------
__device__ __forceinline__ void load_stage(uint32_t stg, int kt, int tid,
                                           int rowBase, int colBase,
                                           const __nv_bfloat16* Ah, const __nv_bfloat16* Al,
                                           const __nv_bfloat16* Bh, const __nv_bfloat16* Bl) {
#pragma unroll
    for (int i = 0; i < 8; ++i) {
        int ch = i * 256 + tid;
        int tile = ch >> 9;
        int r = (ch >> 2) & 127;
        int c = ch & 3;
        const __nv_bfloat16* base = (tile == 0) ? Ah : (tile == 1) ? Al : (tile == 2) ? Bh : Bl;
        int rb = (tile < 2) ? rowBase : colBase;
        const char* src = (const char*)base + ((size_t)(rb + r) * NN + kt * BKt + c * 8) * 2;
        uint32_t dst = stg + tile * TILEB + r * ROWB + c * 16;
        cp16(dst, src);
    }
}

// --------------------------------------------------------------------------
// Static stream-K fused step kernel (R8 partitioning). grid = nsm, block 256.
// Stages in [0, CST_OFF); epilogue Cst in its own region (no aliasing).
// --------------------------------------------------------------------------
__global__ void __launch_bounds__(256, 1) gemm_streamk_kernel(
    int p, int do_mma, int nsm,
    const float* __restrict__ Mv,
    const float* __restrict__ Cc, const float* __restrict__ Amat,
    const float* __restrict__ Bm, const float* __restrict__ Z,
    float* __restrict__ trajh_next,
    float* __restrict__ trajx_cur,
    float* __restrict__ con_cur) {
    extern __shared__ __align__(128) char smem[];
    __shared__ int sflag;
    uint32_t sb = smem_u32(smem);
    float* Cst = (float*)(smem + CST_OFF);
    int tid = threadIdx.x;
    int lane = tid & 31;
    int wid = tid >> 5;
    int q2 = p ^ 1;

    // ---- fused x-update (step t), CTA 0 only ----
    if (blockIdx.x == 0) {
#pragma unroll
        for (int it = 0; it < 2; ++it) {
            int b = tid + it * 256;
            float zh = g_zha[p][b];
            g_zha[p][b] = 0.f;
            float xv0 = g_x[p][b], xv1 = g_x[p][BB + b];
            con_cur[b] = Bm[1] * zh;
            trajx_cur[b] = xv0;
            trajx_cur[BB + b] = xv1;
            g_x[q2][b] = Amat[0] * xv0 + Amat[1] * xv1 + Bm[0] * zh;
            g_x[q2][BB + b] = Amat[2] * xv0 + Amat[3] * xv1 + Bm[1] * zh;
        }
    }
    if (!do_mma) return;

    const __nv_bfloat16* Ah = g_Ahi;
    const __nv_bfloat16* Al = g_Alo;
    const __nv_bfloat16* Bh = g_Bhi[p];
    const __nv_bfloat16* Bl = g_Blo[p];

    int cid = blockIdx.x;
    int c0 = (int)(((long long)cid * TOTC) / nsm);
    int c1 = (int)(((long long)(cid + 1) * TOTC) / nsm);

    int mb = (wid >> 2) * 64;
    int nb = (wid & 3) * 32;
    uint32_t aRow = (uint32_t)(mb + (lane & 15));
    uint32_t aK = (uint32_t)((lane >> 4) * 8);
    uint32_t bRow = (uint32_t)(nb + (lane & 7));
    uint32_t bK = (uint32_t)(((lane >> 3) & 1) * 8);

    while (c0 < c1) {
        int tile = c0 >> 7;
        int kt0 = c0 & 127;
        int kcnt = min(NCHUNK - kt0, c1 - c0);
        int rowBase = (tile >> 2) * BM;
        int colBase = (tile & 3) * BN;

        float acc[4][4][4];
#pragma unroll
        for (int mi = 0; mi < 4; ++mi)
#pragma unroll
            for (int ni = 0; ni < 4; ++ni)
#pragma unroll
                for (int k = 0; k < 4; ++k) acc[mi][ni][k] = 0.f;

        int pre = kcnt < NSTG ? kcnt : NSTG;
#pragma unroll
        for (int s = 0; s < NSTG; ++s) {
            if (s < pre)
                load_stage(sb + s * STAGEB, kt0 + s, tid, rowBase, colBase, Ah, Al, Bh, Bl);
            asm volatile("cp.async.commit_group;" ::: "memory");
        }

        for (int i = 0; i < kcnt; ++i) {
            if (pre == NSTG) {
                asm volatile("cp.async.wait_group %0;" :: "n"(NSTG - 1) : "memory");
            } else {
                asm volatile("cp.async.wait_group 0;" ::: "memory");
            }
            __syncthreads();
            uint32_t stg = sb + (uint32_t)(i & (NSTG - 1)) * STAGEB;
#pragma unroll
            for (int ks = 0; ks < BKt; ks += 16) {
                uint32_t ah[4][4], al2[4][4], bh2[4][2], bl2[4][2];
#pragma unroll
                for (int mi = 0; mi < 4; ++mi) {
                    uint32_t a = stg + (aRow + mi * 16) * ROWB + (aK + ks) * 2;
                    ldsm4(ah[mi], a);
                    ldsm4(al2[mi], a + TILEB);
                }
#pragma unroll
                for (int ni = 0; ni < 4; ++ni) {
                    uint32_t a = stg + 2 * TILEB + (bRow + ni * 8) * ROWB + (bK + ks) * 2;
                    ldsm2(bh2[ni], a);
                    ldsm2(bl2[ni], a + TILEB);
                }
#pragma unroll
                for (int mi = 0; mi < 4; ++mi)
#pragma unroll
                    for (int ni = 0; ni < 4; ++ni) {
                        mma_bf16(acc[mi][ni], ah[mi], bh2[ni]);
                        mma_bf16(acc[mi][ni], ah[mi], bl2[ni]);
                        mma_bf16(acc[mi][ni], al2[mi], bh2[ni]);
                    }
            }
            __syncthreads();
            if (i + NSTG < kcnt)
                load_stage(stg, kt0 + i + NSTG, tid, rowBase, colBase, Ah, Al, Bh, Bl);
            asm volatile("cp.async.commit_group;" ::: "memory");
        }

        // ---- pass 1: frags -> Cst [n][132] (separate region, no drain) ----
#pragma unroll
        for (int mi = 0; mi < 4; ++mi)
#pragma unroll
            for (int ni = 0; ni < 4; ++ni) {
                int m = mb + mi * 16 + (lane >> 2);
                int n = nb + ni * 8 + (lane & 3) * 2;
                Cst[n * 132 + m] = acc[mi][ni][0];
                Cst[(n + 1) * 132 + m] = acc[mi][ni][1];
                Cst[n * 132 + m + 8] = acc[mi][ni][2];
                Cst[(n + 1) * 132 + m + 8] = acc[mi][ni][3];
            }
        __syncthreads();

        // ---- store my partial to my slot (plain, coalesced) ----
        int firstOwner = (int)((((long long)(tile << 7) + 1) * nsm - 1) / TOTC);
        int lastOwner  = (int)((((long long)(tile << 7) + NCHUNK) * nsm - 1) / TOTC);
        int slot = cid - firstOwner;
        int nslots = lastOwner - firstOwner + 1;
        float* part = g_Cpart + ((size_t)(tile * 3 + slot) << 14);
#pragma unroll
        for (int it = 0; it < 16; ++it) {
            int lin = it * 1024 + tid * 4;
            int n = lin >> 7, m = lin & 127;
            *(float4*)&part[lin] = *(float4*)&Cst[n * 132 + m];
        }
        __threadfence();
        __syncthreads();
        if (tid == 0) {
            int old = atomicAdd(&g_cnt[tile], kcnt);
            sflag = (old + kcnt == NCHUNK) ? 1 : 0;
        }
        __syncthreads();

        if (sflag) {
            __threadfence();   // acquire: other slots' data visible
            for (int s = 0; s < nslots; ++s) {
                if (s == slot) continue;
                const float* op = g_Cpart + ((size_t)(tile * 3 + s) << 14);
#pragma unroll
                for (int it = 0; it < 16; ++it) {
                    int lin = it * 1024 + tid * 4;
                    int n = lin >> 7, m = lin & 127;
                    float4 a = *(float4*)&Cst[n * 132 + m];
                    float4 b = *(const float4*)&op[lin];
                    a.x += b.x; a.y += b.y; a.z += b.z; a.w += b.w;
                    *(float4*)&Cst[n * 132 + m] = a;
                }
            }
            __syncthreads();

            // ---- pass 2 (n-major): v = C + DT*M*e; Bhi/Blo out, zh partial
            float CA0 = Cc[0] * Amat[0] + Cc[1] * Amat[2];
            float CA1 = Cc[0] * Amat[1] + Cc[1] * Amat[3];
            {
                int n = tid >> 1;
                int m0 = (tid & 1) * 64;
                float e = CA0 * g_x[p][colBase + n] + CA1 * g_x[p][BB + colBase + n];
                __nv_bfloat16* __restrict__ Bhn = g_Bhi[q2];
                __nv_bfloat16* __restrict__ Bln = g_Blo[q2];
                size_t obase = (size_t)(colBase + n) * NN + rowBase;
                float zp = 0.f;
#pragma unroll
                for (int q = 0; q < 16; ++q) {
                    int m = m0 + q * 4;
                    float4 c = *(float4*)&Cst[n * 132 + m];
                    float4 mv4 = *(const float4*)&Mv[rowBase + m];
                    float4 z4 = *(const float4*)&Z[rowBase + m];
                    float4 v;
                    v.x = c.x + DTc * mv4.x * e;
                    v.y = c.y + DTc * mv4.y * e;
                    v.z = c.z + DTc * mv4.z * e;
                    v.w = c.w + DTc * mv4.w * e;
                    *(float4*)&Cst[n * 132 + m] = v;
                    zp += z4.x * v.x + z4.y * v.y + z4.z * v.z + z4.w * v.w;
                    union { __nv_bfloat16 h[4]; uint2 u; } ph, pl;
                    const float* vp = &v.x;
#pragma unroll
                    for (int j = 0; j < 4; ++j) {
                        __nv_bfloat16 hi = __float2bfloat16(vp[j]);
                        ph.h[j] = hi;
                        pl.h[j] = __float2bfloat16(vp[j] - __bfloat162float(hi));
                    }
                    *(uint2*)&Bhn[obase + m] = ph.u;
                    *(uint2*)&Bln[obase + m] = pl.u;
                }
                zp += __shfl_xor_sync(0xFFFFFFFFu, zp, 1);
                if ((tid & 1) == 0)
                    atomicAdd(&g_zha[q2][colBase + n], zp);
            }
            __syncthreads();

            // ---- pass 3 (m-major): traj_{t+1} h-block ----
            {
                int m = tid >> 1;
                int n0 = (tid & 1) * 64;
                size_t tb = (size_t)(rowBase + m) * BB + colBase + n0;
#pragma unroll
                for (int q = 0; q < 16; ++q) {
                    float4 v;
                    v.x = Cst[(n0 + q * 4 + 0) * 132 + m];
                    v.y = Cst[(n0 + q * 4 + 1) * 132 + m];
                    v.z = Cst[(n0 + q * 4 + 2) * 132 + m];
                    v.w = Cst[(n0 + q * 4 + 3) * 132 + m];
                    *(float4*)&trajh_next[tb + q * 4] = v;
                }
            }
            if (tid == 0) atomicExch(&g_cnt[tile], 0);   // restore for next step
        }
        __syncthreads();   // Cst reuse safe before next segment
        c0 += kcnt;
    }
}

// --------------------------------------------------------------------------
extern "C" void kernel_launch(void* const* d_in, const int* in_sizes, int n_in,
                              void* d_out, int out_size) {
    const float* x0 = (const float*)d_in[0];
    const float* x1 = (const float*)d_in[1];
    const float* h0 = (const float*)d_in[2];
    const float* A  = (const float*)d_in[3];
    const float* Bm = (const float*)d_in[4];
    const float* C  = (const float*)d_in[5];
    const float* Mv = (const float*)d_in[6];
    const float* Z  = (const float*)d_in[7];
    const float* U  = (const float*)d_in[8];
    const float* V  = (const float*)d_in[9];
    const float* W  = (const float*)d_in[10];

    long long per_step_full = (long long)BB * (NN + 2 + 1);
    int steps = (int)((long long)out_size / per_step_full);
    if ((long long)steps * per_step_full != (long long)out_size)
        steps = (int)((long long)out_size / ((long long)BB * (NN + 2)));

    float* out  = (float*)d_out;
    float* traj = out;
    float* con  = out + (size_t)steps * (NN + 2) * BB;

    int nsm = 0;
    cudaDeviceGetAttribute(&nsm, cudaDevAttrMultiProcessorCount, 0);
    if (nsm < 8 || nsm > 512) nsm = 148;

    cudaFuncSetAttribute(gemm_streamk_kernel,
                         cudaFuncAttributeMaxDynamicSharedMemorySize, SMEM_BYTES);

    build_split_kernel<<<dim3(NN / 4 / 256, NN), 256>>>(W, U, V, Mv, Z, C, Bm);
    init_all_kernel<<<dim3(NN / 32, BB / 32), dim3(32, 8)>>>(h0, x0, x1, Z, traj + 2 * BB);

    for (int t = 0; t < steps; ++t) {
        int p = t & 1;
        int do_mma = (t < steps - 1);
        float* traj_t = traj + (size_t)t * (NN + 2) * BB;
        float* trajh_next = traj + (size_t)(t + 1) * (NN + 2) * BB + 2 * BB;
        if (!do_mma) trajh_next = traj_t + 2 * BB;   // unused, keep in-bounds
        gemm_streamk_kernel<<<nsm, 256, SMEM_BYTES>>>(
            p, do_mma, nsm, Mv, C, A, Bm, Z,
            trajh_next, traj_t, con + (size_t)t * BB);
    }
}

// round 12
// speedup vs baseline: 1.4457x; 1.0152x over previous
#include <cuda_runtime.h>
#include <cuda_bf16.h>
#include <cstdint>

#define NN 4096
#define BB 512
#define DTc 0.1f

// GEMM tiling (mma.sync bf16)
#define BM 128
#define BN 128
#define BKt 32
#define NCHUNK 128                   // K-chunks per tile (4096/32)
#define NTILES 128                   // 32 M x 4 N
#define TOTC (NTILES * NCHUNK)       // 16384
#define ROWB 80
#define TILEB (128 * ROWB)
#define STAGEB (4 * TILEB)           // 40960
#define NSTG 3
#define CST_OFF (NSTG * STAGEB)      // 122880
#define SMEM_BYTES (CST_OFF + 128 * 132 * 4)   // 190464

// --------------------------------------------------------------------------
__device__ __align__(256) __nv_bfloat16 g_Ahi[(size_t)NN * NN];    // 32 MB
__device__ __align__(256) __nv_bfloat16 g_Alo[(size_t)NN * NN];    // 32 MB
__device__ __align__(256) __nv_bfloat16 g_Bhi[2][(size_t)BB * NN]; // 2x4 MB
__device__ __align__(256) __nv_bfloat16 g_Blo[2][(size_t)BB * NN]; // 2x4 MB
__device__ __align__(256) float g_Cpart[(size_t)NTILES * 3 * 128 * 128]; // 25.2 MB
__device__ int g_cnt[NTILES];        // zero-init; kernel restores zeros
__device__ float g_x[2][2 * BB];
__device__ float g_zha[2][BB];

// --------------------------------------------------------------------------
__device__ __forceinline__ uint32_t smem_u32(const void* p) {
    return (uint32_t)__cvta_generic_to_shared((void*)p);
}
__device__ __forceinline__ void cp16(uint32_t dst, const void* src) {
    asm volatile("cp.async.cg.shared.global [%0], [%1], 16;" :: "r"(dst), "l"(src) : "memory");
}
__device__ __forceinline__ void ldsm4(uint32_t* r, uint32_t a) {
    asm volatile("ldmatrix.sync.aligned.m8n8.x4.shared.b16 {%0,%1,%2,%3}, [%4];"
                 : "=r"(r[0]), "=r"(r[1]), "=r"(r[2]), "=r"(r[3]) : "r"(a));
}
__device__ __forceinline__ void ldsm2(uint32_t* r, uint32_t a) {
    asm volatile("ldmatrix.sync.aligned.m8n8.x2.shared.b16 {%0,%1}, [%2];"
                 : "=r"(r[0]), "=r"(r[1]) : "r"(a));
}
__device__ __forceinline__ void mma_bf16(float* d, const uint32_t* a, const uint32_t* b) {
    asm("mma.sync.aligned.m16n8k16.row.col.f32.bf16.bf16.f32 "
        "{%0,%1,%2,%3}, {%4,%5,%6,%7}, {%8,%9}, {%0,%1,%2,%3};"
        : "+f"(d[0]), "+f"(d[1]), "+f"(d[2]), "+f"(d[3])
        : "r"(a[0]), "r"(a[1]), "r"(a[2]), "r"(a[3]), "r"(b[0]), "r"(b[1]));
}

// --------------------------------------------------------------------------
// Build A_hi/A_lo (bf16 split of P22); zero zh accumulators + counters.
// --------------------------------------------------------------------------
__global__ void build_split_kernel(const float* __restrict__ W,
                                   const float* __restrict__ U,
                                   const float* __restrict__ V,
                                   const float* __restrict__ Mv,
                                   const float* __restrict__ Z,
                                   const float* __restrict__ Cc,
                                   const float* __restrict__ Bm) {
    if (blockIdx.x == 0 && blockIdx.y == 0) {
        int tIdx = threadIdx.x;
        g_zha[0][tIdx] = 0.f;       g_zha[1][tIdx] = 0.f;
        g_zha[0][tIdx + 256] = 0.f; g_zha[1][tIdx + 256] = 0.f;
        if (tIdx < NTILES) g_cnt[tIdx] = 0;
    }
    int i = blockIdx.y;
    int j = (blockIdx.x * blockDim.x + threadIdx.x) * 4;
    float cb = Cc[0] * Bm[0] + Cc[1] * Bm[1];
    float mi = Mv[i];
    float u0 = U[i * 4 + 0], u1 = U[i * 4 + 1], u2 = U[i * 4 + 2], u3 = U[i * 4 + 3];
    float4 w = *(const float4*)(W + (size_t)i * NN + j);
    const float* wp = &w.x;
    union { __nv_bfloat16 h[4]; uint2 u; } ph, pl;
#pragma unroll
    for (int jj = 0; jj < 4; ++jj) {
        int jc = j + jj;
        float4 vv = *(const float4*)(V + (size_t)jc * 4);
        float uv = u0 * vv.x + u1 * vv.y + u2 * vv.z + u3 * vv.w;
        float val = DTc * (wp[jj] + uv) + cb * mi * Z[jc];
        if (jc == i) val += 1.0f - DTc;
        __nv_bfloat16 hi = __float2bfloat16(val);
        ph.h[jj] = hi;
        pl.h[jj] = __float2bfloat16(val - __bfloat162float(hi));
    }
    *(uint2*)(g_Ahi + (size_t)i * NN + j) = ph.u;
    *(uint2*)(g_Alo + (size_t)i * NN + j) = pl.u;
}

// --------------------------------------------------------------------------
// init_all: h0 -> traj_0 h-block + transposed bf16 split + zh0 + x init
// --------------------------------------------------------------------------
__global__ void init_all_kernel(const float* __restrict__ h0,
                                const float* __restrict__ x0,
                                const float* __restrict__ x1,
                                const float* __restrict__ Z,
                                float* __restrict__ traj0h) {
    __shared__ float t[32][33];
    __shared__ float zs[8][33];
    int m0 = blockIdx.x * 32, b0 = blockIdx.y * 32;
    int tx = threadIdx.x, ty = threadIdx.y;
    if (blockIdx.x == 0 && blockIdx.y == 0) {
        int tid = ty * 32 + tx;
#pragma unroll
        for (int it = 0; it < 2; ++it) {
            int b = tid + it * 256;
            g_x[0][b] = x0[b];
            g_x[0][BB + b] = x1[b];
        }
    }
#pragma unroll
    for (int j = 0; j < 32; j += 8) {
        size_t a = (size_t)(m0 + ty + j) * BB + b0 + tx;
        float v = h0[a];
        traj0h[a] = v;
        t[ty + j][tx] = v;
    }
    __syncthreads();
    {
        float s = 0.f;
#pragma unroll
        for (int i = 0; i < 4; ++i) {
            int r = ty * 4 + i;
            s = fmaf(Z[m0 + r], t[r][tx], s);
        }
        zs[ty][tx] = s;
    }
#pragma unroll
    for (int j = 0; j < 32; j += 8) {
        float v = t[tx][ty + j];
        size_t o = (size_t)(b0 + ty + j) * NN + m0 + tx;
        __nv_bfloat16 hi = __float2bfloat16(v);
        g_Bhi[0][o] = hi;
        g_Blo[0][o] = __float2bfloat16(v - __bfloat162float(hi));
    }
    __syncthreads();
    if (ty == 0) {
        float s = 0.f;
#pragma unroll
        for (int r = 0; r < 8; ++r) s += zs[r][tx];
        atomicAdd(&g_zha[0][b0 + tx], s);
    }
}

// --------------------------------------------------------------------------
__device__ __forceinline__ void load_stage(uint32_t stg, int kt, int tid,
                                           int rowBase, int colBase,
                                           const __nv_bfloat16* Ah, const __nv_bfloat16* Al,
                                           const __nv_bfloat16* Bh, const __nv_bfloat16* Bl) {
#pragma unroll
    for (int i = 0; i < 8; ++i) {
        int ch = i * 256 + tid;
        int tile = ch >> 9;
        int r = (ch >> 2) & 127;
        int c = ch & 3;
        const __nv_bfloat16* base = (tile == 0) ? Ah : (tile == 1) ? Al : (tile == 2) ? Bh : Bl;
        int rb = (tile < 2) ? rowBase : colBase;
        const char* src = (const char*)base + ((size_t)(rb + r) * NN + kt * BKt + c * 8) * 2;
        uint32_t dst = stg + tile * TILEB + r * ROWB + c * 16;
        cp16(dst, src);
    }
}

// --------------------------------------------------------------------------
// Static stream-K fused step kernel (R8 partitioning, NSTG=3) with
// next-segment prefetch issued BEFORE the epilogue (Cst is a separate smem
// region so prefetch and epilogue never alias). grid = nsm, block 256.
// --------------------------------------------------------------------------
__global__ void __launch_bounds__(256, 1) gemm_streamk_kernel(
    int p, int do_mma, int nsm,
    const float* __restrict__ Mv,
    const float* __restrict__ Cc, const float* __restrict__ Amat,
    const float* __restrict__ Bm, const float* __restrict__ Z,
    float* __restrict__ trajh_next,
    float* __restrict__ trajx_cur,
    float* __restrict__ con_cur) {
    extern __shared__ __align__(128) char smem[];
    __shared__ int sflag;
    uint32_t sb = smem_u32(smem);
    float* Cst = (float*)(smem + CST_OFF);
    int tid = threadIdx.x;
    int lane = tid & 31;
    int wid = tid >> 5;
    int q2 = p ^ 1;

    // ---- fused x-update (step t), CTA 0 only ----
    if (blockIdx.x == 0) {
#pragma unroll
        for (int it = 0; it < 2; ++it) {
            int b = tid + it * 256;
            float zh = g_zha[p][b];
            g_zha[p][b] = 0.f;
            float xv0 = g_x[p][b], xv1 = g_x[p][BB + b];
            con_cur[b] = Bm[1] * zh;
            trajx_cur[b] = xv0;
            trajx_cur[BB + b] = xv1;
            g_x[q2][b] = Amat[0] * xv0 + Amat[1] * xv1 + Bm[0] * zh;
            g_x[q2][BB + b] = Amat[2] * xv0 + Amat[3] * xv1 + Bm[1] * zh;
        }
    }
    if (!do_mma) return;

    const __nv_bfloat16* Ah = g_Ahi;
    const __nv_bfloat16* Al = g_Alo;
    const __nv_bfloat16* Bh = g_Bhi[p];
    const __nv_bfloat16* Bl = g_Blo[p];

    int cid = blockIdx.x;
    int c0 = (int)(((long long)cid * TOTC) / nsm);
    int c1 = (int)(((long long)(cid + 1) * TOTC) / nsm);

    int mb = (wid >> 2) * 64;
    int nb = (wid & 3) * 32;
    uint32_t aRow = (uint32_t)(mb + (lane & 15));
    uint32_t aK = (uint32_t)((lane >> 4) * 8);
    uint32_t bRow = (uint32_t)(nb + (lane & 7));
    uint32_t bK = (uint32_t)(((lane >> 3) & 1) * 8);

    int preLoaded = 0;   // stages already filled by prev-iteration prefetch
    int pre = 0;

    while (c0 < c1) {
        int tile = c0 >> 7;
        int kt0 = c0 & 127;
        int kcnt = min(NCHUNK - kt0, c1 - c0);
        int rowBase = (tile >> 2) * BM;
        int colBase = (tile & 3) * BN;

        float acc[4][4][4];
#pragma unroll
        for (int mi = 0; mi < 4; ++mi)
#pragma unroll
            for (int ni = 0; ni < 4; ++ni)
#pragma unroll
                for (int k = 0; k < 4; ++k) acc[mi][ni][k] = 0.f;

        if (!preLoaded) {
            pre = kcnt < NSTG ? kcnt : NSTG;
#pragma unroll
            for (int s = 0; s < NSTG; ++s) {
                if (s < pre)
                    load_stage(sb + s * STAGEB, kt0 + s, tid, rowBase, colBase, Ah, Al, Bh, Bl);
                asm volatile("cp.async.commit_group;" ::: "memory");
            }
        }

        for (int i = 0; i < kcnt; ++i) {
            if (pre == NSTG) {
                asm volatile("cp.async.wait_group %0;" :: "n"(NSTG - 1) : "memory");
            } else {
                asm volatile("cp.async.wait_group 0;" ::: "memory");
            }
            __syncthreads();
            uint32_t stg = sb + (uint32_t)(i % NSTG) * STAGEB;
#pragma unroll
            for (int ks = 0; ks < BKt; ks += 16) {
                uint32_t ah[4][4], al2[4][4], bh2[4][2], bl2[4][2];
#pragma unroll
                for (int mi = 0; mi < 4; ++mi) {
                    uint32_t a = stg + (aRow + mi * 16) * ROWB + (aK + ks) * 2;
                    ldsm4(ah[mi], a);
                    ldsm4(al2[mi], a + TILEB);
                }
#pragma unroll
                for (int ni = 0; ni < 4; ++ni) {
                    uint32_t a = stg + 2 * TILEB + (bRow + ni * 8) * ROWB + (bK + ks) * 2;
                    ldsm2(bh2[ni], a);
                    ldsm2(bl2[ni], a + TILEB);
                }
#pragma unroll
                for (int mi = 0; mi < 4; ++mi)
#pragma unroll
                    for (int ni = 0; ni < 4; ++ni) {
                        mma_bf16(acc[mi][ni], ah[mi], bh2[ni]);
                        mma_bf16(acc[mi][ni], ah[mi], bl2[ni]);
                        mma_bf16(acc[mi][ni], al2[mi], bh2[ni]);
                    }
            }
            __syncthreads();
            if (i + NSTG < kcnt)
                load_stage(stg, kt0 + i + NSTG, tid, rowBase, colBase, Ah, Al, Bh, Bl);
            asm volatile("cp.async.commit_group;" ::: "memory");
        }

        // ---- prefetch NEXT segment's prologue under the epilogue ----
        int nc0 = c0 + kcnt;
        if (nc0 < c1) {
            int nTile = nc0 >> 7;
            int nkt0 = nc0 & 127;
            int nkcnt = min(NCHUNK - nkt0, c1 - nc0);
            int nRowB = (nTile >> 2) * BM;
            int nColB = (nTile & 3) * BN;
            int npre = nkcnt < NSTG ? nkcnt : NSTG;
#pragma unroll
            for (int s = 0; s < NSTG; ++s) {
                if (s < npre)
                    load_stage(sb + s * STAGEB, nkt0 + s, tid, nRowB, nColB, Ah, Al, Bh, Bl);
                asm volatile("cp.async.commit_group;" ::: "memory");
            }
            preLoaded = 1;
            pre = npre;
        } else {
            preLoaded = 0;
        }

        // ---- pass 1: frags -> Cst [n][132] (separate region) ----
#pragma unroll
        for (int mi = 0; mi < 4; ++mi)
#pragma unroll
            for (int ni = 0; ni < 4; ++ni) {
                int m = mb + mi * 16 + (lane >> 2);
                int n = nb + ni * 8 + (lane & 3) * 2;
                Cst[n * 132 + m] = acc[mi][ni][0];
                Cst[(n + 1) * 132 + m] = acc[mi][ni][1];
                Cst[n * 132 + m + 8] = acc[mi][ni][2];
                Cst[(n + 1) * 132 + m + 8] = acc[mi][ni][3];
            }
        __syncthreads();

        // ---- store my partial to my slot (plain, coalesced) ----
        int firstOwner = (int)((((long long)(tile << 7) + 1) * nsm - 1) / TOTC);
        int lastOwner  = (int)((((long long)(tile << 7) + NCHUNK) * nsm - 1) / TOTC);
        int slot = cid - firstOwner;
        int nslots = lastOwner - firstOwner + 1;
        float* part = g_Cpart + ((size_t)(tile * 3 + slot) << 14);
#pragma unroll
        for (int it = 0; it < 16; ++it) {
            int lin = it * 1024 + tid * 4;
            int n = lin >> 7, m = lin & 127;
            *(float4*)&part[lin] = *(float4*)&Cst[n * 132 + m];
        }
        __threadfence();
        __syncthreads();
        if (tid == 0) {
            int old = atomicAdd(&g_cnt[tile], kcnt);
            sflag = (old + kcnt == NCHUNK) ? 1 : 0;
        }
        __syncthreads();

        if (sflag) {
            __threadfence();   // acquire: other slots' data visible
            for (int s = 0; s < nslots; ++s) {
                if (s == slot) continue;
                const float* op = g_Cpart + ((size_t)(tile * 3 + s) << 14);
#pragma unroll
                for (int it = 0; it < 16; ++it) {
                    int lin = it * 1024 + tid * 4;
                    int n = lin >> 7, m = lin & 127;
                    float4 a = *(float4*)&Cst[n * 132 + m];
                    float4 b = *(const float4*)&op[lin];
                    a.x += b.x; a.y += b.y; a.z += b.z; a.w += b.w;
                    *(float4*)&Cst[n * 132 + m] = a;
                }
            }
            __syncthreads();

            // ---- pass 2 (n-major): v = C + DT*M*e; Bhi/Blo out, zh partial
            float CA0 = Cc[0] * Amat[0] + Cc[1] * Amat[2];
            float CA1 = Cc[0] * Amat[1] + Cc[1] * Amat[3];
            {
                int n = tid >> 1;
                int m0 = (tid & 1) * 64;
                float e = CA0 * g_x[p][colBase + n] + CA1 * g_x[p][BB + colBase + n];
                __nv_bfloat16* __restrict__ Bhn = g_Bhi[q2];
                __nv_bfloat16* __restrict__ Bln = g_Blo[q2];
                size_t obase = (size_t)(colBase + n) * NN + rowBase;
                float zp = 0.f;
#pragma unroll
                for (int q = 0; q < 16; ++q) {
                    int m = m0 + q * 4;
                    float4 c = *(float4*)&Cst[n * 132 + m];
                    float4 mv4 = *(const float4*)&Mv[rowBase + m];
                    float4 z4 = *(const float4*)&Z[rowBase + m];
                    float4 v;
                    v.x = c.x + DTc * mv4.x * e;
                    v.y = c.y + DTc * mv4.y * e;
                    v.z = c.z + DTc * mv4.z * e;
                    v.w = c.w + DTc * mv4.w * e;
                    *(float4*)&Cst[n * 132 + m] = v;
                    zp += z4.x * v.x + z4.y * v.y + z4.z * v.z + z4.w * v.w;
                    union { __nv_bfloat16 h[4]; uint2 u; } ph, pl;
                    const float* vp = &v.x;
#pragma unroll
                    for (int j = 0; j < 4; ++j) {
                        __nv_bfloat16 hi = __float2bfloat16(vp[j]);
                        ph.h[j] = hi;
                        pl.h[j] = __float2bfloat16(vp[j] - __bfloat162float(hi));
                    }
                    *(uint2*)&Bhn[obase + m] = ph.u;
                    *(uint2*)&Bln[obase + m] = pl.u;
                }
                zp += __shfl_xor_sync(0xFFFFFFFFu, zp, 1);
                if ((tid & 1) == 0)
                    atomicAdd(&g_zha[q2][colBase + n], zp);
            }
            __syncthreads();

            // ---- pass 3 (m-major): traj_{t+1} h-block ----
            {
                int m = tid >> 1;
                int n0 = (tid & 1) * 64;
                size_t tb = (size_t)(rowBase + m) * BB + colBase + n0;
#pragma unroll
                for (int q = 0; q < 16; ++q) {
                    float4 v;
                    v.x = Cst[(n0 + q * 4 + 0) * 132 + m];
                    v.y = Cst[(n0 + q * 4 + 1) * 132 + m];
                    v.z = Cst[(n0 + q * 4 + 2) * 132 + m];
                    v.w = Cst[(n0 + q * 4 + 3) * 132 + m];
                    *(float4*)&trajh_next[tb + q * 4] = v;
                }
            }
            if (tid == 0) atomicExch(&g_cnt[tile], 0);   // restore for next step
        }
        __syncthreads();   // Cst reuse safe before next segment
        c0 = nc0;
    }
}

// --------------------------------------------------------------------------
extern "C" void kernel_launch(void* const* d_in, const int* in_sizes, int n_in,
                              void* d_out, int out_size) {
    const float* x0 = (const float*)d_in[0];
    const float* x1 = (const float*)d_in[1];
    const float* h0 = (const float*)d_in[2];
    const float* A  = (const float*)d_in[3];
    const float* Bm = (const float*)d_in[4];
    const float* C  = (const float*)d_in[5];
    const float* Mv = (const float*)d_in[6];
    const float* Z  = (const float*)d_in[7];
    const float* U  = (const float*)d_in[8];
    const float* V  = (const float*)d_in[9];
    const float* W  = (const float*)d_in[10];

    long long per_step_full = (long long)BB * (NN + 2 + 1);
    int steps = (int)((long long)out_size / per_step_full);
    if ((long long)steps * per_step_full != (long long)out_size)
        steps = (int)((long long)out_size / ((long long)BB * (NN + 2)));

    float* out  = (float*)d_out;
    float* traj = out;
    float* con  = out + (size_t)steps * (NN + 2) * BB;

    int nsm = 0;
    cudaDeviceGetAttribute(&nsm, cudaDevAttrMultiProcessorCount, 0);
    if (nsm < 8 || nsm > 512) nsm = 148;

    cudaFuncSetAttribute(gemm_streamk_kernel,
                         cudaFuncAttributeMaxDynamicSharedMemorySize, SMEM_BYTES);

    build_split_kernel<<<dim3(NN / 4 / 256, NN), 256>>>(W, U, V, Mv, Z, C, Bm);
    init_all_kernel<<<dim3(NN / 32, BB / 32), dim3(32, 8)>>>(h0, x0, x1, Z, traj + 2 * BB);

    for (int t = 0; t < steps; ++t) {
        int p = t & 1;
        int do_mma = (t < steps - 1);
        float* traj_t = traj + (size_t)t * (NN + 2) * BB;
        float* trajh_next = traj + (size_t)(t + 1) * (NN + 2) * BB + 2 * BB;
        if (!do_mma) trajh_next = traj_t + 2 * BB;   // unused, keep in-bounds
        gemm_streamk_kernel<<<nsm, 256, SMEM_BYTES>>>(
            p, do_mma, nsm, Mv, C, A, Bm, Z,
            trajh_next, traj_t, con + (size_t)t * BB);
    }
}

// round 13
// speedup vs baseline: 1.4885x; 1.0296x over previous
#include <cuda_runtime.h>
#include <cuda_bf16.h>
#include <cstdint>

#define NN 4096
#define BB 512
#define DTc 0.1f

// GEMM tiling (mma.sync bf16)
#define BM 128
#define BN 128
#define BKt 32
#define NCHUNK 128                   // K-chunks per tile (4096/32)
#define NTILES 128                   // 32 M x 4 N
#define TOTC (NTILES * NCHUNK)       // 16384
#define ROWB 80
#define TILEB (128 * ROWB)
#define STAGEB (4 * TILEB)           // 40960
#define NSTG 3
#define CST_OFF (NSTG * STAGEB)      // 122880
#define SMEM_BYTES (CST_OFF + 128 * 132 * 4)   // 190464

// --------------------------------------------------------------------------
__device__ __align__(256) __nv_bfloat16 g_Ahi[(size_t)NN * NN];    // 32 MB
__device__ __align__(256) __nv_bfloat16 g_Alo[(size_t)NN * NN];    // 32 MB
__device__ __align__(256) __nv_bfloat16 g_Bhi[2][(size_t)BB * NN]; // 2x4 MB
__device__ __align__(256) __nv_bfloat16 g_Blo[2][(size_t)BB * NN]; // 2x4 MB
__device__ __align__(256) float g_Cpart[(size_t)NTILES * 3 * 128 * 128]; // 25.2 MB
__device__ int g_cnt[NTILES];        // zero-init; kernel restores zeros
__device__ float g_x[2][2 * BB];
__device__ float g_zha[2][BB];

// --------------------------------------------------------------------------
__device__ __forceinline__ uint32_t smem_u32(const void* p) {
    return (uint32_t)__cvta_generic_to_shared((void*)p);
}
__device__ __forceinline__ void cp16(uint32_t dst, const void* src) {
    asm volatile("cp.async.cg.shared.global [%0], [%1], 16;" :: "r"(dst), "l"(src) : "memory");
}
__device__ __forceinline__ void ldsm4(uint32_t* r, uint32_t a) {
    asm volatile("ldmatrix.sync.aligned.m8n8.x4.shared.b16 {%0,%1,%2,%3}, [%4];"
                 : "=r"(r[0]), "=r"(r[1]), "=r"(r[2]), "=r"(r[3]) : "r"(a));
}
__device__ __forceinline__ void ldsm2(uint32_t* r, uint32_t a) {
    asm volatile("ldmatrix.sync.aligned.m8n8.x2.shared.b16 {%0,%1}, [%2];"
                 : "=r"(r[0]), "=r"(r[1]) : "r"(a));
}
__device__ __forceinline__ void mma_bf16(float* d, const uint32_t* a, const uint32_t* b) {
    asm("mma.sync.aligned.m16n8k16.row.col.f32.bf16.bf16.f32 "
        "{%0,%1,%2,%3}, {%4,%5,%6,%7}, {%8,%9}, {%0,%1,%2,%3};"
        : "+f"(d[0]), "+f"(d[1]), "+f"(d[2]), "+f"(d[3])
        : "r"(a[0]), "r"(a[1]), "r"(a[2]), "r"(a[3]), "r"(b[0]), "r"(b[1]));
}

// --------------------------------------------------------------------------
// Build A_hi/A_lo (bf16 split of P22); zero zh accumulators + counters.
// --------------------------------------------------------------------------
__global__ void build_split_kernel(const float* __restrict__ W,
                                   const float* __restrict__ U,
                                   const float* __restrict__ V,
                                   const float* __restrict__ Mv,
                                   const float* __restrict__ Z,
                                   const float* __restrict__ Cc,
                                   const float* __restrict__ Bm) {
    if (blockIdx.x == 0 && blockIdx.y == 0) {
        int tIdx = threadIdx.x;
        g_zha[0][tIdx] = 0.f;       g_zha[1][tIdx] = 0.f;
        g_zha[0][tIdx + 256] = 0.f; g_zha[1][tIdx + 256] = 0.f;
        if (tIdx < NTILES) g_cnt[tIdx] = 0;
    }
    int i = blockIdx.y;
    int j = (blockIdx.x * blockDim.x + threadIdx.x) * 4;
    float cb = Cc[0] * Bm[0] + Cc[1] * Bm[1];
    float mi = Mv[i];
    float u0 = U[i * 4 + 0], u1 = U[i * 4 + 1], u2 = U[i * 4 + 2], u3 = U[i * 4 + 3];
    float4 w = *(const float4*)(W + (size_t)i * NN + j);
    const float* wp = &w.x;
    union { __nv_bfloat16 h[4]; uint2 u; } ph, pl;
#pragma unroll
    for (int jj = 0; jj < 4; ++jj) {
        int jc = j + jj;
        float4 vv = *(const float4*)(V + (size_t)jc * 4);
        float uv = u0 * vv.x + u1 * vv.y + u2 * vv.z + u3 * vv.w;
        float val = DTc * (wp[jj] + uv) + cb * mi * Z[jc];
        if (jc == i) val += 1.0f - DTc;
        __nv_bfloat16 hi = __float2bfloat16(val);
        ph.h[jj] = hi;
        pl.h[jj] = __float2bfloat16(val - __bfloat162float(hi));
    }
    *(uint2*)(g_Ahi + (size_t)i * NN + j) = ph.u;
    *(uint2*)(g_Alo + (size_t)i * NN + j) = pl.u;
}

// --------------------------------------------------------------------------
// init_all: h0 -> traj_0 h-block + transposed bf16 split + zh0 + x init
// --------------------------------------------------------------------------
__global__ void init_all_kernel(const float* __restrict__ h0,
                                const float* __restrict__ x0,
                                const float* __restrict__ x1,
                                const float* __restrict__ Z,
                                float* __restrict__ traj0h) {
    __shared__ float t[32][33];
    __shared__ float zs[8][33];
    int m0 = blockIdx.x * 32, b0 = blockIdx.y * 32;
    int tx = threadIdx.x, ty = threadIdx.y;
    if (blockIdx.x == 0 && blockIdx.y == 0) {
        int tid = ty * 32 + tx;
#pragma unroll
        for (int it = 0; it < 2; ++it) {
            int b = tid + it * 256;
            g_x[0][b] = x0[b];
            g_x[0][BB + b] = x1[b];
        }
    }
#pragma unroll
    for (int j = 0; j < 32; j += 8) {
        size_t a = (size_t)(m0 + ty + j) * BB + b0 + tx;
        float v = h0[a];
        traj0h[a] = v;
        t[ty + j][tx] = v;
    }
    __syncthreads();
    {
        float s = 0.f;
#pragma unroll
        for (int i = 0; i < 4; ++i) {
            int r = ty * 4 + i;
            s = fmaf(Z[m0 + r], t[r][tx], s);
        }
        zs[ty][tx] = s;
    }
#pragma unroll
    for (int j = 0; j < 32; j += 8) {
        float v = t[tx][ty + j];
        size_t o = (size_t)(b0 + ty + j) * NN + m0 + tx;
        __nv_bfloat16 hi = __float2bfloat16(v);
        g_Bhi[0][o] = hi;
        g_Blo[0][o] = __float2bfloat16(v - __bfloat162float(hi));
    }
    __syncthreads();
    if (ty == 0) {
        float s = 0.f;
#pragma unroll
        for (int r = 0; r < 8; ++r) s += zs[r][tx];
        atomicAdd(&g_zha[0][b0 + tx], s);
    }
}

// --------------------------------------------------------------------------
__device__ __forceinline__ void load_stage(uint32_t stg, int kt, int tid,
                                           int rowBase, int colBase,
                                           const __nv_bfloat16* Ah, const __nv_bfloat16* Al,
                                           const __nv_bfloat16* Bh, const __nv_bfloat16* Bl) {
#pragma unroll
    for (int i = 0; i < 8; ++i) {
        int ch = i * 256 + tid;
        int tile = ch >> 9;
        int r = (ch >> 2) & 127;
        int c = ch & 3;
        const __nv_bfloat16* base = (tile == 0) ? Ah : (tile == 1) ? Al : (tile == 2) ? Bh : Bl;
        int rb = (tile < 2) ? rowBase : colBase;
        const char* src = (const char*)base + ((size_t)(rb + r) * NN + kt * BKt + c * 8) * 2;
        uint32_t dst = stg + tile * TILEB + r * ROWB + c * 16;
        cp16(dst, src);
    }
}

// --------------------------------------------------------------------------
// Static stream-K fused step kernel (R8 partitioning, NSTG=3), CUTLASS-style
// SINGLE-BARRIER mainloop: at iter i, barrier, then load chunk i+NSTG-1 into
// slot (i-1)%NSTG (drained last iter, proven by this barrier), then consume
// slot i%NSTG. grid = nsm, block 256.
// --------------------------------------------------------------------------
__global__ void __launch_bounds__(256, 1) gemm_streamk_kernel(
    int p, int do_mma, int nsm,
    const float* __restrict__ Mv,
    const float* __restrict__ Cc, const float* __restrict__ Amat,
    const float* __restrict__ Bm, const float* __restrict__ Z,
    float* __restrict__ trajh_next,
    float* __restrict__ trajx_cur,
    float* __restrict__ con_cur) {
    extern __shared__ __align__(128) char smem[];
    __shared__ int sflag;
    uint32_t sb = smem_u32(smem);
    float* Cst = (float*)(smem + CST_OFF);
    int tid = threadIdx.x;
    int lane = tid & 31;
    int wid = tid >> 5;
    int q2 = p ^ 1;

    // ---- fused x-update (step t), CTA 0 only ----
    if (blockIdx.x == 0) {
#pragma unroll
        for (int it = 0; it < 2; ++it) {
            int b = tid + it * 256;
            float zh = g_zha[p][b];
            g_zha[p][b] = 0.f;
            float xv0 = g_x[p][b], xv1 = g_x[p][BB + b];
            con_cur[b] = Bm[1] * zh;
            trajx_cur[b] = xv0;
            trajx_cur[BB + b] = xv1;
            g_x[q2][b] = Amat[0] * xv0 + Amat[1] * xv1 + Bm[0] * zh;
            g_x[q2][BB + b] = Amat[2] * xv0 + Amat[3] * xv1 + Bm[1] * zh;
        }
    }
    if (!do_mma) return;

    const __nv_bfloat16* Ah = g_Ahi;
    const __nv_bfloat16* Al = g_Alo;
    const __nv_bfloat16* Bh = g_Bhi[p];
    const __nv_bfloat16* Bl = g_Blo[p];

    int cid = blockIdx.x;
    int c0 = (int)(((long long)cid * TOTC) / nsm);
    int c1 = (int)(((long long)(cid + 1) * TOTC) / nsm);

    int mb = (wid >> 2) * 64;
    int nb = (wid & 3) * 32;
    uint32_t aRow = (uint32_t)(mb + (lane & 15));
    uint32_t aK = (uint32_t)((lane >> 4) * 8);
    uint32_t bRow = (uint32_t)(nb + (lane & 7));
    uint32_t bK = (uint32_t)(((lane >> 3) & 1) * 8);

    while (c0 < c1) {
        int tile = c0 >> 7;
        int kt0 = c0 & 127;
        int kcnt = min(NCHUNK - kt0, c1 - c0);
        int rowBase = (tile >> 2) * BM;
        int colBase = (tile & 3) * BN;

        float acc[4][4][4];
#pragma unroll
        for (int mi = 0; mi < 4; ++mi)
#pragma unroll
            for (int ni = 0; ni < 4; ++ni)
#pragma unroll
                for (int k = 0; k < 4; ++k) acc[mi][ni][k] = 0.f;

        // prologue: NSTG-1 chunks
        int pre = kcnt < (NSTG - 1) ? kcnt : (NSTG - 1);
#pragma unroll
        for (int s = 0; s < NSTG - 1; ++s) {
            if (s < pre)
                load_stage(sb + s * STAGEB, kt0 + s, tid, rowBase, colBase, Ah, Al, Bh, Bl);
            asm volatile("cp.async.commit_group;" ::: "memory");
        }

        for (int i = 0; i < kcnt; ++i) {
            if (pre == NSTG - 1) {
                asm volatile("cp.async.wait_group %0;" :: "n"(NSTG - 2) : "memory");
            } else {
                asm volatile("cp.async.wait_group 0;" ::: "memory");
            }
            __syncthreads();   // chunk i resident; slot (i-1)%NSTG drained by all warps

            int ld = i + NSTG - 1;
            if (ld < kcnt)
                load_stage(sb + (uint32_t)(ld % NSTG) * STAGEB, kt0 + ld, tid,
                           rowBase, colBase, Ah, Al, Bh, Bl);
            asm volatile("cp.async.commit_group;" ::: "memory");

            uint32_t stg = sb + (uint32_t)(i % NSTG) * STAGEB;
#pragma unroll
            for (int ks = 0; ks < BKt; ks += 16) {
                uint32_t ah[4][4], al2[4][4], bh2[4][2], bl2[4][2];
#pragma unroll
                for (int mi = 0; mi < 4; ++mi) {
                    uint32_t a = stg + (aRow + mi * 16) * ROWB + (aK + ks) * 2;
                    ldsm4(ah[mi], a);
                    ldsm4(al2[mi], a + TILEB);
                }
#pragma unroll
                for (int ni = 0; ni < 4; ++ni) {
                    uint32_t a = stg + 2 * TILEB + (bRow + ni * 8) * ROWB + (bK + ks) * 2;
                    ldsm2(bh2[ni], a);
                    ldsm2(bl2[ni], a + TILEB);
                }
#pragma unroll
                for (int mi = 0; mi < 4; ++mi)
#pragma unroll
                    for (int ni = 0; ni < 4; ++ni) {
                        mma_bf16(acc[mi][ni], ah[mi], bh2[ni]);
                        mma_bf16(acc[mi][ni], ah[mi], bl2[ni]);
                        mma_bf16(acc[mi][ni], al2[mi], bh2[ni]);
                    }
            }
        }

        // ---- pass 1: frags -> Cst [n][132] (separate region) ----
#pragma unroll
        for (int mi = 0; mi < 4; ++mi)
#pragma unroll
            for (int ni = 0; ni < 4; ++ni) {
                int m = mb + mi * 16 + (lane >> 2);
                int n = nb + ni * 8 + (lane & 3) * 2;
                Cst[n * 132 + m] = acc[mi][ni][0];
                Cst[(n + 1) * 132 + m] = acc[mi][ni][1];
                Cst[n * 132 + m + 8] = acc[mi][ni][2];
                Cst[(n + 1) * 132 + m + 8] = acc[mi][ni][3];
            }
        __syncthreads();

        // ---- store my partial to my slot (plain, coalesced) ----
        int firstOwner = (int)((((long long)(tile << 7) + 1) * nsm - 1) / TOTC);
        int lastOwner  = (int)((((long long)(tile << 7) + NCHUNK) * nsm - 1) / TOTC);
        int slot = cid - firstOwner;
        int nslots = lastOwner - firstOwner + 1;
        float* part = g_Cpart + ((size_t)(tile * 3 + slot) << 14);
#pragma unroll
        for (int it = 0; it < 16; ++it) {
            int lin = it * 1024 + tid * 4;
            int n = lin >> 7, m = lin & 127;
            *(float4*)&part[lin] = *(float4*)&Cst[n * 132 + m];
        }
        __threadfence();
        __syncthreads();
        if (tid == 0) {
            int old = atomicAdd(&g_cnt[tile], kcnt);
            sflag = (old + kcnt == NCHUNK) ? 1 : 0;
        }
        __syncthreads();

        if (sflag) {
            __threadfence();   // acquire: other slots' data visible
            for (int s = 0; s < nslots; ++s) {
                if (s == slot) continue;
                const float* op = g_Cpart + ((size_t)(tile * 3 + s) << 14);
#pragma unroll
                for (int it = 0; it < 16; ++it) {
                    int lin = it * 1024 + tid * 4;
                    int n = lin >> 7, m = lin & 127;
                    float4 a = *(float4*)&Cst[n * 132 + m];
                    float4 b = *(const float4*)&op[lin];
                    a.x += b.x; a.y += b.y; a.z += b.z; a.w += b.w;
                    *(float4*)&Cst[n * 132 + m] = a;
                }
            }
            __syncthreads();

            // ---- pass 2 (n-major): v = C + DT*M*e; Bhi/Blo out, zh partial
            float CA0 = Cc[0] * Amat[0] + Cc[1] * Amat[2];
            float CA1 = Cc[0] * Amat[1] + Cc[1] * Amat[3];
            {
                int n = tid >> 1;
                int m0 = (tid & 1) * 64;
                float e = CA0 * g_x[p][colBase + n] + CA1 * g_x[p][BB + colBase + n];
                __nv_bfloat16* __restrict__ Bhn = g_Bhi[q2];
                __nv_bfloat16* __restrict__ Bln = g_Blo[q2];
                size_t obase = (size_t)(colBase + n) * NN + rowBase;
                float zp = 0.f;
#pragma unroll
                for (int q = 0; q < 16; ++q) {
                    int m = m0 + q * 4;
                    float4 c = *(float4*)&Cst[n * 132 + m];
                    float4 mv4 = *(const float4*)&Mv[rowBase + m];
                    float4 z4 = *(const float4*)&Z[rowBase + m];
                    float4 v;
                    v.x = c.x + DTc * mv4.x * e;
                    v.y = c.y + DTc * mv4.y * e;
                    v.z = c.z + DTc * mv4.z * e;
                    v.w = c.w + DTc * mv4.w * e;
                    *(float4*)&Cst[n * 132 + m] = v;
                    zp += z4.x * v.x + z4.y * v.y + z4.z * v.z + z4.w * v.w;
                    union { __nv_bfloat16 h[4]; uint2 u; } ph, pl;
                    const float* vp = &v.x;
#pragma unroll
                    for (int j = 0; j < 4; ++j) {
                        __nv_bfloat16 hi = __float2bfloat16(vp[j]);
                        ph.h[j] = hi;
                        pl.h[j] = __float2bfloat16(vp[j] - __bfloat162float(hi));
                    }
                    *(uint2*)&Bhn[obase + m] = ph.u;
                    *(uint2*)&Bln[obase + m] = pl.u;
                }
                zp += __shfl_xor_sync(0xFFFFFFFFu, zp, 1);
                if ((tid & 1) == 0)
                    atomicAdd(&g_zha[q2][colBase + n], zp);
            }
            __syncthreads();

            // ---- pass 3 (m-major): traj_{t+1} h-block ----
            {
                int m = tid >> 1;
                int n0 = (tid & 1) * 64;
                size_t tb = (size_t)(rowBase + m) * BB + colBase + n0;
#pragma unroll
                for (int q = 0; q < 16; ++q) {
                    float4 v;
                    v.x = Cst[(n0 + q * 4 + 0) * 132 + m];
                    v.y = Cst[(n0 + q * 4 + 1) * 132 + m];
                    v.z = Cst[(n0 + q * 4 + 2) * 132 + m];
                    v.w = Cst[(n0 + q * 4 + 3) * 132 + m];
                    *(float4*)&trajh_next[tb + q * 4] = v;
                }
            }
            if (tid == 0) atomicExch(&g_cnt[tile], 0);   // restore for next step
        }
        __syncthreads();   // Cst reuse safe before next segment
        c0 += kcnt;
    }
}

// --------------------------------------------------------------------------
extern "C" void kernel_launch(void* const* d_in, const int* in_sizes, int n_in,
                              void* d_out, int out_size) {
    const float* x0 = (const float*)d_in[0];
    const float* x1 = (const float*)d_in[1];
    const float* h0 = (const float*)d_in[2];
    const float* A  = (const float*)d_in[3];
    const float* Bm = (const float*)d_in[4];
    const float* C  = (const float*)d_in[5];
    const float* Mv = (const float*)d_in[6];
    const float* Z  = (const float*)d_in[7];
    const float* U  = (const float*)d_in[8];
    const float* V  = (const float*)d_in[9];
    const float* W  = (const float*)d_in[10];

    long long per_step_full = (long long)BB * (NN + 2 + 1);
    int steps = (int)((long long)out_size / per_step_full);
    if ((long long)steps * per_step_full != (long long)out_size)
        steps = (int)((long long)out_size / ((long long)BB * (NN + 2)));

    float* out  = (float*)d_out;
    float* traj = out;
    float* con  = out + (size_t)steps * (NN + 2) * BB;

    int nsm = 0;
    cudaDeviceGetAttribute(&nsm, cudaDevAttrMultiProcessorCount, 0);
    if (nsm < 8 || nsm > 512) nsm = 148;

    cudaFuncSetAttribute(gemm_streamk_kernel,
                         cudaFuncAttributeMaxDynamicSharedMemorySize, SMEM_BYTES);

    build_split_kernel<<<dim3(NN / 4 / 256, NN), 256>>>(W, U, V, Mv, Z, C, Bm);
    init_all_kernel<<<dim3(NN / 32, BB / 32), dim3(32, 8)>>>(h0, x0, x1, Z, traj + 2 * BB);

    for (int t = 0; t < steps; ++t) {
        int p = t & 1;
        int do_mma = (t < steps - 1);
        float* traj_t = traj + (size_t)t * (NN + 2) * BB;
        float* trajh_next = traj + (size_t)(t + 1) * (NN + 2) * BB + 2 * BB;
        if (!do_mma) trajh_next = traj_t + 2 * BB;   // unused, keep in-bounds
        gemm_streamk_kernel<<<nsm, 256, SMEM_BYTES>>>(
            p, do_mma, nsm, Mv, C, A, Bm, Z,
            trajh_next, traj_t, con + (size_t)t * BB);
    }
}

// round 14
// speedup vs baseline: 1.5091x; 1.0139x over previous
#include <cuda_runtime.h>
#include <cuda_bf16.h>
#include <cstdint>

#define NN 4096
#define BB 512
#define DTc 0.1f

// GEMM tiling (mma.sync bf16)
#define BM 128
#define BN 128
#define BKt 32                       // 32-k granularity of load_stage / smem layout
#define NCHUNK 64                    // K64-chunks per tile (4096/64)
#define NTILES 128                   // 32 M x 4 N
#define TOTC (NTILES * NCHUNK)       // 8192
#define ROWB 80
#define TILEB (128 * ROWB)
#define STAGEB (4 * TILEB)           // 40960 (one 32-k half)
#define CHUNKB (2 * STAGEB)          // 81920 (one K64 chunk slot)
#define NSTG 2
#define CST_OFF (NSTG * CHUNKB)      // 163840
#define SMEM_BYTES (CST_OFF + 128 * 132 * 4)   // 231424

// --------------------------------------------------------------------------
__device__ __align__(256) __nv_bfloat16 g_Ahi[(size_t)NN * NN];    // 32 MB
__device__ __align__(256) __nv_bfloat16 g_Alo[(size_t)NN * NN];    // 32 MB
__device__ __align__(256) __nv_bfloat16 g_Bhi[2][(size_t)BB * NN]; // 2x4 MB
__device__ __align__(256) __nv_bfloat16 g_Blo[2][(size_t)BB * NN]; // 2x4 MB
__device__ __align__(256) float g_Cpart[(size_t)NTILES * 3 * 128 * 128]; // 25.2 MB
__device__ int g_cnt[NTILES];        // zero-init; kernel restores zeros
__device__ float g_x[2][2 * BB];
__device__ float g_zha[2][BB];

// --------------------------------------------------------------------------
__device__ __forceinline__ uint32_t smem_u32(const void* p) {
    return (uint32_t)__cvta_generic_to_shared((void*)p);
}
__device__ __forceinline__ void cp16(uint32_t dst, const void* src) {
    asm volatile("cp.async.cg.shared.global [%0], [%1], 16;" :: "r"(dst), "l"(src) : "memory");
}
__device__ __forceinline__ void ldsm4(uint32_t* r, uint32_t a) {
    asm volatile("ldmatrix.sync.aligned.m8n8.x4.shared.b16 {%0,%1,%2,%3}, [%4];"
                 : "=r"(r[0]), "=r"(r[1]), "=r"(r[2]), "=r"(r[3]) : "r"(a));
}
__device__ __forceinline__ void ldsm2(uint32_t* r, uint32_t a) {
    asm volatile("ldmatrix.sync.aligned.m8n8.x2.shared.b16 {%0,%1}, [%2];"
                 : "=r"(r[0]), "=r"(r[1]) : "r"(a));
}
__device__ __forceinline__ void mma_bf16(float* d, const uint32_t* a, const uint32_t* b) {
    asm("mma.sync.aligned.m16n8k16.row.col.f32.bf16.bf16.f32 "
        "{%0,%1,%2,%3}, {%4,%5,%6,%7}, {%8,%9}, {%0,%1,%2,%3};"
        : "+f"(d[0]), "+f"(d[1]), "+f"(d[2]), "+f"(d[3])
        : "r"(a[0]), "r"(a[1]), "r"(a[2]), "r"(a[3]), "r"(b[0]), "r"(b[1]));
}

// --------------------------------------------------------------------------
// Build A_hi/A_lo (bf16 split of P22); zero zh accumulators + counters.
// --------------------------------------------------------------------------
__global__ void build_split_kernel(const float* __restrict__ W,
                                   const float* __restrict__ U,
                                   const float* __restrict__ V,
                                   const float* __restrict__ Mv,
                                   const float* __restrict__ Z,
                                   const float* __restrict__ Cc,
                                   const float* __restrict__ Bm) {
    if (blockIdx.x == 0 && blockIdx.y == 0) {
        int tIdx = threadIdx.x;
        g_zha[0][tIdx] = 0.f;       g_zha[1][tIdx] = 0.f;
        g_zha[0][tIdx + 256] = 0.f; g_zha[1][tIdx + 256] = 0.f;
        if (tIdx < NTILES) g_cnt[tIdx] = 0;
    }
    int i = blockIdx.y;
    int j = (blockIdx.x * blockDim.x + threadIdx.x) * 4;
    float cb = Cc[0] * Bm[0] + Cc[1] * Bm[1];
    float mi = Mv[i];
    float u0 = U[i * 4 + 0], u1 = U[i * 4 + 1], u2 = U[i * 4 + 2], u3 = U[i * 4 + 3];
    float4 w = *(const float4*)(W + (size_t)i * NN + j);
    const float* wp = &w.x;
    union { __nv_bfloat16 h[4]; uint2 u; } ph, pl;
#pragma unroll
    for (int jj = 0; jj < 4; ++jj) {
        int jc = j + jj;
        float4 vv = *(const float4*)(V + (size_t)jc * 4);
        float uv = u0 * vv.x + u1 * vv.y + u2 * vv.z + u3 * vv.w;
        float val = DTc * (wp[jj] + uv) + cb * mi * Z[jc];
        if (jc == i) val += 1.0f - DTc;
        __nv_bfloat16 hi = __float2bfloat16(val);
        ph.h[jj] = hi;
        pl.h[jj] = __float2bfloat16(val - __bfloat162float(hi));
    }
    *(uint2*)(g_Ahi + (size_t)i * NN + j) = ph.u;
    *(uint2*)(g_Alo + (size_t)i * NN + j) = pl.u;
}

// --------------------------------------------------------------------------
// init_all: h0 -> traj_0 h-block + transposed bf16 split + zh0 + x init
// --------------------------------------------------------------------------
__global__ void init_all_kernel(const float* __restrict__ h0,
                                const float* __restrict__ x0,
                                const float* __restrict__ x1,
                                const float* __restrict__ Z,
                                float* __restrict__ traj0h) {
    __shared__ float t[32][33];
    __shared__ float zs[8][33];
    int m0 = blockIdx.x * 32, b0 = blockIdx.y * 32;
    int tx = threadIdx.x, ty = threadIdx.y;
    if (blockIdx.x == 0 && blockIdx.y == 0) {
        int tid = ty * 32 + tx;
#pragma unroll
        for (int it = 0; it < 2; ++it) {
            int b = tid + it * 256;
            g_x[0][b] = x0[b];
            g_x[0][BB + b] = x1[b];
        }
    }
#pragma unroll
    for (int j = 0; j < 32; j += 8) {
        size_t a = (size_t)(m0 + ty + j) * BB + b0 + tx;
        float v = h0[a];
        traj0h[a] = v;
        t[ty + j][tx] = v;
    }
    __syncthreads();
    {
        float s = 0.f;
#pragma unroll
        for (int i = 0; i < 4; ++i) {
            int r = ty * 4 + i;
            s = fmaf(Z[m0 + r], t[r][tx], s);
        }
        zs[ty][tx] = s;
    }
#pragma unroll
    for (int j = 0; j < 32; j += 8) {
        float v = t[tx][ty + j];
        size_t o = (size_t)(b0 + ty + j) * NN + m0 + tx;
        __nv_bfloat16 hi = __float2bfloat16(v);
        g_Bhi[0][o] = hi;
        g_Blo[0][o] = __float2bfloat16(v - __bfloat162float(hi));
    }
    __syncthreads();
    if (ty == 0) {
        float s = 0.f;
#pragma unroll
        for (int r = 0; r < 8; ++r) s += zs[r][tx];
        atomicAdd(&g_zha[0][b0 + tx], s);
    }
}

// --------------------------------------------------------------------------
// Load one 32-k half (kt in 32-k units) into a 40960-byte half-stage.
// --------------------------------------------------------------------------
__device__ __forceinline__ void load_stage(uint32_t stg, int kt, int tid,
                                           int rowBase, int colBase,
                                           const __nv_bfloat16* Ah, const __nv_bfloat16* Al,
                                           const __nv_bfloat16* Bh, const __nv_bfloat16* Bl) {
#pragma unroll
    for (int i = 0; i < 8; ++i) {
        int ch = i * 256 + tid;
        int tile = ch >> 9;
        int r = (ch >> 2) & 127;
        int c = ch & 3;
        const __nv_bfloat16* base = (tile == 0) ? Ah : (tile == 1) ? Al : (tile == 2) ? Bh : Bl;
        int rb = (tile < 2) ? rowBase : colBase;
        const char* src = (const char*)base + ((size_t)(rb + r) * NN + kt * BKt + c * 8) * 2;
        uint32_t dst = stg + tile * TILEB + r * ROWB + c * 16;
        cp16(dst, src);
    }
}

// Load one full K64 chunk (kt64 in 64-k units) into chunk slot; ONE commit group.
__device__ __forceinline__ void load_chunk64(uint32_t slotBase, int kt64, int tid,
                                             int rowBase, int colBase,
                                             const __nv_bfloat16* Ah, const __nv_bfloat16* Al,
                                             const __nv_bfloat16* Bh, const __nv_bfloat16* Bl) {
    load_stage(slotBase,          kt64 * 2,     tid, rowBase, colBase, Ah, Al, Bh, Bl);
    load_stage(slotBase + STAGEB, kt64 * 2 + 1, tid, rowBase, colBase, Ah, Al, Bh, Bl);
    asm volatile("cp.async.commit_group;" ::: "memory");
}

// --------------------------------------------------------------------------
// Static stream-K fused step kernel; K64 chunks, NSTG=2, single barrier per
// chunk: at iter i — wait_group(0) (chunk i resident), barrier (slot of
// chunk i-1 drained by all warps), issue chunk i+1 into that slot, consume.
// grid = nsm, block 256.
// --------------------------------------------------------------------------
__global__ void __launch_bounds__(256, 1) gemm_streamk_kernel(
    int p, int do_mma, int nsm,
    const float* __restrict__ Mv,
    const float* __restrict__ Cc, const float* __restrict__ Amat,
    const float* __restrict__ Bm, const float* __restrict__ Z,
    float* __restrict__ trajh_next,
    float* __restrict__ trajx_cur,
    float* __restrict__ con_cur) {
    extern __shared__ __align__(128) char smem[];
    __shared__ int sflag;
    uint32_t sb = smem_u32(smem);
    float* Cst = (float*)(smem + CST_OFF);
    int tid = threadIdx.x;
    int lane = tid & 31;
    int wid = tid >> 5;
    int q2 = p ^ 1;

    // ---- fused x-update (step t), CTA 0 only ----
    if (blockIdx.x == 0) {
#pragma unroll
        for (int it = 0; it < 2; ++it) {
            int b = tid + it * 256;
            float zh = g_zha[p][b];
            g_zha[p][b] = 0.f;
            float xv0 = g_x[p][b], xv1 = g_x[p][BB + b];
            con_cur[b] = Bm[1] * zh;
            trajx_cur[b] = xv0;
            trajx_cur[BB + b] = xv1;
            g_x[q2][b] = Amat[0] * xv0 + Amat[1] * xv1 + Bm[0] * zh;
            g_x[q2][BB + b] = Amat[2] * xv0 + Amat[3] * xv1 + Bm[1] * zh;
        }
    }
    if (!do_mma) return;

    const __nv_bfloat16* Ah = g_Ahi;
    const __nv_bfloat16* Al = g_Alo;
    const __nv_bfloat16* Bh = g_Bhi[p];
    const __nv_bfloat16* Bl = g_Blo[p];

    int cid = blockIdx.x;
    int c0 = (int)(((long long)cid * TOTC) / nsm);
    int c1 = (int)(((long long)(cid + 1) * TOTC) / nsm);

    int mb = (wid >> 2) * 64;
    int nb = (wid & 3) * 32;
    uint32_t aRow = (uint32_t)(mb + (lane & 15));
    uint32_t aK = (uint32_t)((lane >> 4) * 8);
    uint32_t bRow = (uint32_t)(nb + (lane & 7));
    uint32_t bK = (uint32_t)(((lane >> 3) & 1) * 8);

    while (c0 < c1) {
        int tile = c0 >> 6;               // K64 units: 64 chunks per tile
        int kt0 = c0 & 63;
        int kcnt = min(NCHUNK - kt0, c1 - c0);
        int rowBase = (tile >> 2) * BM;
        int colBase = (tile & 3) * BN;

        float acc[4][4][4];
#pragma unroll
        for (int mi = 0; mi < 4; ++mi)
#pragma unroll
            for (int ni = 0; ni < 4; ++ni)
#pragma unroll
                for (int k = 0; k < 4; ++k) acc[mi][ni][k] = 0.f;

        // prologue: chunk kt0 into slot 0
        load_chunk64(sb, kt0, tid, rowBase, colBase, Ah, Al, Bh, Bl);

        for (int i = 0; i < kcnt; ++i) {
            asm volatile("cp.async.wait_group 0;" ::: "memory");  // chunk i resident
            __syncthreads();   // visible to all warps; slot of chunk i-1 drained

            if (i + 1 < kcnt)
                load_chunk64(sb + (uint32_t)((i + 1) & 1) * CHUNKB, kt0 + i + 1, tid,
                             rowBase, colBase, Ah, Al, Bh, Bl);

            uint32_t slot = sb + (uint32_t)(i & 1) * CHUNKB;
#pragma unroll
            for (int ks4 = 0; ks4 < 4; ++ks4) {
                uint32_t stg = slot + (uint32_t)(ks4 >> 1) * STAGEB;
                int ks = (ks4 & 1) * 16;
                uint32_t ah[4][4], al2[4][4], bh2[4][2], bl2[4][2];
#pragma unroll
                for (int mi = 0; mi < 4; ++mi) {
                    uint32_t a = stg + (aRow + mi * 16) * ROWB + (aK + ks) * 2;
                    ldsm4(ah[mi], a);
                    ldsm4(al2[mi], a + TILEB);
                }
#pragma unroll
                for (int ni = 0; ni < 4; ++ni) {
                    uint32_t a = stg + 2 * TILEB + (bRow + ni * 8) * ROWB + (bK + ks) * 2;
                    ldsm2(bh2[ni], a);
                    ldsm2(bl2[ni], a + TILEB);
                }
#pragma unroll
                for (int mi = 0; mi < 4; ++mi)
#pragma unroll
                    for (int ni = 0; ni < 4; ++ni) {
                        mma_bf16(acc[mi][ni], ah[mi], bh2[ni]);
                        mma_bf16(acc[mi][ni], ah[mi], bl2[ni]);
                        mma_bf16(acc[mi][ni], al2[mi], bh2[ni]);
                    }
            }
        }

        // ---- pass 1: frags -> Cst [n][132] (separate region) ----
#pragma unroll
        for (int mi = 0; mi < 4; ++mi)
#pragma unroll
            for (int ni = 0; ni < 4; ++ni) {
                int m = mb + mi * 16 + (lane >> 2);
                int n = nb + ni * 8 + (lane & 3) * 2;
                Cst[n * 132 + m] = acc[mi][ni][0];
                Cst[(n + 1) * 132 + m] = acc[mi][ni][1];
                Cst[n * 132 + m + 8] = acc[mi][ni][2];
                Cst[(n + 1) * 132 + m + 8] = acc[mi][ni][3];
            }
        __syncthreads();

        // ---- store my partial to my slot (plain, coalesced) ----
        int firstOwner = (int)((((long long)(tile << 6) + 1) * nsm - 1) / TOTC);
        int lastOwner  = (int)((((long long)(tile << 6) + NCHUNK) * nsm - 1) / TOTC);
        int slot = cid - firstOwner;
        int nslots = lastOwner - firstOwner + 1;
        float* part = g_Cpart + ((size_t)(tile * 3 + slot) << 14);
#pragma unroll
        for (int it = 0; it < 16; ++it) {
            int lin = it * 1024 + tid * 4;
            int n = lin >> 7, m = lin & 127;
            *(float4*)&part[lin] = *(float4*)&Cst[n * 132 + m];
        }
        __threadfence();
        __syncthreads();
        if (tid == 0) {
            int old = atomicAdd(&g_cnt[tile], kcnt);
            sflag = (old + kcnt == NCHUNK) ? 1 : 0;
        }
        __syncthreads();

        if (sflag) {
            __threadfence();   // acquire: other slots' data visible
            for (int s = 0; s < nslots; ++s) {
                if (s == slot) continue;
                const float* op = g_Cpart + ((size_t)(tile * 3 + s) << 14);
#pragma unroll
                for (int it = 0; it < 16; ++it) {
                    int lin = it * 1024 + tid * 4;
                    int n = lin >> 7, m = lin & 127;
                    float4 a = *(float4*)&Cst[n * 132 + m];
                    float4 b = *(const float4*)&op[lin];
                    a.x += b.x; a.y += b.y; a.z += b.z; a.w += b.w;
                    *(float4*)&Cst[n * 132 + m] = a;
                }
            }
            __syncthreads();

            // ---- pass 2 (n-major): v = C + DT*M*e; Bhi/Blo out, zh partial
            float CA0 = Cc[0] * Amat[0] + Cc[1] * Amat[2];
            float CA1 = Cc[0] * Amat[1] + Cc[1] * Amat[3];
            {
                int n = tid >> 1;
                int m0 = (tid & 1) * 64;
                float e = CA0 * g_x[p][colBase + n] + CA1 * g_x[p][BB + colBase + n];
                __nv_bfloat16* __restrict__ Bhn = g_Bhi[q2];
                __nv_bfloat16* __restrict__ Bln = g_Blo[q2];
                size_t obase = (size_t)(colBase + n) * NN + rowBase;
                float zp = 0.f;
#pragma unroll
                for (int q = 0; q < 16; ++q) {
                    int m = m0 + q * 4;
                    float4 c = *(float4*)&Cst[n * 132 + m];
                    float4 mv4 = *(const float4*)&Mv[rowBase + m];
                    float4 z4 = *(const float4*)&Z[rowBase + m];
                    float4 v;
                    v.x = c.x + DTc * mv4.x * e;
                    v.y = c.y + DTc * mv4.y * e;
                    v.z = c.z + DTc * mv4.z * e;
                    v.w = c.w + DTc * mv4.w * e;
                    *(float4*)&Cst[n * 132 + m] = v;
                    zp += z4.x * v.x + z4.y * v.y + z4.z * v.z + z4.w * v.w;
                    union { __nv_bfloat16 h[4]; uint2 u; } ph, pl;
                    const float* vp = &v.x;
#pragma unroll
                    for (int j = 0; j < 4; ++j) {
                        __nv_bfloat16 hi = __float2bfloat16(vp[j]);
                        ph.h[j] = hi;
                        pl.h[j] = __float2bfloat16(vp[j] - __bfloat162float(hi));
                    }
                    *(uint2*)&Bhn[obase + m] = ph.u;
                    *(uint2*)&Bln[obase + m] = pl.u;
                }
                zp += __shfl_xor_sync(0xFFFFFFFFu, zp, 1);
                if ((tid & 1) == 0)
                    atomicAdd(&g_zha[q2][colBase + n], zp);
            }
            __syncthreads();

            // ---- pass 3 (m-major): traj_{t+1} h-block ----
            {
                int m = tid >> 1;
                int n0 = (tid & 1) * 64;
                size_t tb = (size_t)(rowBase + m) * BB + colBase + n0;
#pragma unroll
                for (int q = 0; q < 16; ++q) {
                    float4 v;
                    v.x = Cst[(n0 + q * 4 + 0) * 132 + m];
                    v.y = Cst[(n0 + q * 4 + 1) * 132 + m];
                    v.z = Cst[(n0 + q * 4 + 2) * 132 + m];
                    v.w = Cst[(n0 + q * 4 + 3) * 132 + m];
                    *(float4*)&trajh_next[tb + q * 4] = v;
                }
            }
            if (tid == 0) atomicExch(&g_cnt[tile], 0);   // restore for next step
        }
        __syncthreads();   // Cst reuse safe before next segment
        c0 += kcnt;
    }
}

// --------------------------------------------------------------------------
extern "C" void kernel_launch(void* const* d_in, const int* in_sizes, int n_in,
                              void* d_out, int out_size) {
    const float* x0 = (const float*)d_in[0];
    const float* x1 = (const float*)d_in[1];
    const float* h0 = (const float*)d_in[2];
    const float* A  = (const float*)d_in[3];
    const float* Bm = (const float*)d_in[4];
    const float* C  = (const float*)d_in[5];
    const float* Mv = (const float*)d_in[6];
    const float* Z  = (const float*)d_in[7];
    const float* U  = (const float*)d_in[8];
    const float* V  = (const float*)d_in[9];
    const float* W  = (const float*)d_in[10];

    long long per_step_full = (long long)BB * (NN + 2 + 1);
    int steps = (int)((long long)out_size / per_step_full);
    if ((long long)steps * per_step_full != (long long)out_size)
        steps = (int)((long long)out_size / ((long long)BB * (NN + 2)));

    float* out  = (float*)d_out;
    float* traj = out;
    float* con  = out + (size_t)steps * (NN + 2) * BB;

    int nsm = 0;
    cudaDeviceGetAttribute(&nsm, cudaDevAttrMultiProcessorCount, 0);
    if (nsm < 8 || nsm > 512) nsm = 148;

    cudaFuncSetAttribute(gemm_streamk_kernel,
                         cudaFuncAttributeMaxDynamicSharedMemorySize, SMEM_BYTES);

    build_split_kernel<<<dim3(NN / 4 / 256, NN), 256>>>(W, U, V, Mv, Z, C, Bm);
    init_all_kernel<<<dim3(NN / 32, BB / 32), dim3(32, 8)>>>(h0, x0, x1, Z, traj + 2 * BB);

    for (int t = 0; t < steps; ++t) {
        int p = t & 1;
        int do_mma = (t < steps - 1);
        float* traj_t = traj + (size_t)t * (NN + 2) * BB;
        float* trajh_next = traj + (size_t)(t + 1) * (NN + 2) * BB + 2 * BB;
        if (!do_mma) trajh_next = traj_t + 2 * BB;   // unused, keep in-bounds
        gemm_streamk_kernel<<<nsm, 256, SMEM_BYTES>>>(
            p, do_mma, nsm, Mv, C, A, Bm, Z,
            trajh_next, traj_t, con + (size_t)t * BB);
    }
}

// round 15
// speedup vs baseline: 1.5504x; 1.0273x over previous
#include <cuda_runtime.h>
#include <cuda_bf16.h>
#include <cstdint>

#define NN 4096
#define BB 512
#define DTc 0.1f

// GEMM tiling (mma.sync bf16)
#define BM 128
#define BN 128
#define BKt 32                       // 32-k granularity of load_stage / smem layout
#define NCHUNK 64                    // K64-chunks per tile (4096/64)
#define NTILES 128                   // 32 M x 4 N
#define TOTC (NTILES * NCHUNK)       // 8192
#define ROWB 80
#define TILEB (128 * ROWB)
#define STAGEB (4 * TILEB)           // 40960 (one 32-k half)
#define CHUNKB (2 * STAGEB)          // 81920 (one K64 chunk slot)
#define NSTG 2
#define CST_OFF (NSTG * CHUNKB)      // 163840
#define SMEM_BYTES (CST_OFF + 128 * 132 * 4)   // 231424

// --------------------------------------------------------------------------
__device__ __align__(256) __nv_bfloat16 g_Ahi[(size_t)NN * NN];    // 32 MB
__device__ __align__(256) __nv_bfloat16 g_Alo[(size_t)NN * NN];    // 32 MB
__device__ __align__(256) __nv_bfloat16 g_Bhi[2][(size_t)BB * NN]; // 2x4 MB
__device__ __align__(256) __nv_bfloat16 g_Blo[2][(size_t)BB * NN]; // 2x4 MB
__device__ __align__(256) float g_Cpart[(size_t)NTILES * 3 * 128 * 128]; // 25.2 MB
__device__ int g_cnt[NTILES];        // zero-init; kernel restores zeros
__device__ float g_x[2][2 * BB];
__device__ float g_zha[2][BB];

// --------------------------------------------------------------------------
__device__ __forceinline__ uint32_t smem_u32(const void* p) {
    return (uint32_t)__cvta_generic_to_shared((void*)p);
}
__device__ __forceinline__ void cp16(uint32_t dst, const void* src) {
    asm volatile("cp.async.cg.shared.global [%0], [%1], 16;" :: "r"(dst), "l"(src) : "memory");
}
__device__ __forceinline__ void ldsm4(uint32_t* r, uint32_t a) {
    asm volatile("ldmatrix.sync.aligned.m8n8.x4.shared.b16 {%0,%1,%2,%3}, [%4];"
                 : "=r"(r[0]), "=r"(r[1]), "=r"(r[2]), "=r"(r[3]) : "r"(a));
}
__device__ __forceinline__ void mma_bf16(float* d, const uint32_t* a, const uint32_t* b) {
    asm("mma.sync.aligned.m16n8k16.row.col.f32.bf16.bf16.f32 "
        "{%0,%1,%2,%3}, {%4,%5,%6,%7}, {%8,%9}, {%0,%1,%2,%3};"
        : "+f"(d[0]), "+f"(d[1]), "+f"(d[2]), "+f"(d[3])
        : "r"(a[0]), "r"(a[1]), "r"(a[2]), "r"(a[3]), "r"(b[0]), "r"(b[1]));
}

// --------------------------------------------------------------------------
// Build A_hi/A_lo (bf16 split of P22); zero zh accumulators + counters.
// --------------------------------------------------------------------------
__global__ void build_split_kernel(const float* __restrict__ W,
                                   const float* __restrict__ U,
                                   const float* __restrict__ V,
                                   const float* __restrict__ Mv,
                                   const float* __restrict__ Z,
                                   const float* __restrict__ Cc,
                                   const float* __restrict__ Bm) {
    if (blockIdx.x == 0 && blockIdx.y == 0) {
        int tIdx = threadIdx.x;
        g_zha[0][tIdx] = 0.f;       g_zha[1][tIdx] = 0.f;
        g_zha[0][tIdx + 256] = 0.f; g_zha[1][tIdx + 256] = 0.f;
        if (tIdx < NTILES) g_cnt[tIdx] = 0;
    }
    int i = blockIdx.y;
    int j = (blockIdx.x * blockDim.x + threadIdx.x) * 4;
    float cb = Cc[0] * Bm[0] + Cc[1] * Bm[1];
    float mi = Mv[i];
    float u0 = U[i * 4 + 0], u1 = U[i * 4 + 1], u2 = U[i * 4 + 2], u3 = U[i * 4 + 3];
    float4 w = *(const float4*)(W + (size_t)i * NN + j);
    const float* wp = &w.x;
    union { __nv_bfloat16 h[4]; uint2 u; } ph, pl;
#pragma unroll
    for (int jj = 0; jj < 4; ++jj) {
        int jc = j + jj;
        float4 vv = *(const float4*)(V + (size_t)jc * 4);
        float uv = u0 * vv.x + u1 * vv.y + u2 * vv.z + u3 * vv.w;
        float val = DTc * (wp[jj] + uv) + cb * mi * Z[jc];
        if (jc == i) val += 1.0f - DTc;
        __nv_bfloat16 hi = __float2bfloat16(val);
        ph.h[jj] = hi;
        pl.h[jj] = __float2bfloat16(val - __bfloat162float(hi));
    }
    *(uint2*)(g_Ahi + (size_t)i * NN + j) = ph.u;
    *(uint2*)(g_Alo + (size_t)i * NN + j) = pl.u;
}

// --------------------------------------------------------------------------
// init_all: h0 -> traj_0 h-block + transposed bf16 split + zh0 + x init
// --------------------------------------------------------------------------
__global__ void init_all_kernel(const float* __restrict__ h0,
                                const float* __restrict__ x0,
                                const float* __restrict__ x1,
                                const float* __restrict__ Z,
                                float* __restrict__ traj0h) {
    __shared__ float t[32][33];
    __shared__ float zs[8][33];
    int m0 = blockIdx.x * 32, b0 = blockIdx.y * 32;
    int tx = threadIdx.x, ty = threadIdx.y;
    if (blockIdx.x == 0 && blockIdx.y == 0) {
        int tid = ty * 32 + tx;
#pragma unroll
        for (int it = 0; it < 2; ++it) {
            int b = tid + it * 256;
            g_x[0][b] = x0[b];
            g_x[0][BB + b] = x1[b];
        }
    }
#pragma unroll
    for (int j = 0; j < 32; j += 8) {
        size_t a = (size_t)(m0 + ty + j) * BB + b0 + tx;
        float v = h0[a];
        traj0h[a] = v;
        t[ty + j][tx] = v;
    }
    __syncthreads();
    {
        float s = 0.f;
#pragma unroll
        for (int i = 0; i < 4; ++i) {
            int r = ty * 4 + i;
            s = fmaf(Z[m0 + r], t[r][tx], s);
        }
        zs[ty][tx] = s;
    }
#pragma unroll
    for (int j = 0; j < 32; j += 8) {
        float v = t[tx][ty + j];
        size_t o = (size_t)(b0 + ty + j) * NN + m0 + tx;
        __nv_bfloat16 hi = __float2bfloat16(v);
        g_Bhi[0][o] = hi;
        g_Blo[0][o] = __float2bfloat16(v - __bfloat162float(hi));
    }
    __syncthreads();
    if (ty == 0) {
        float s = 0.f;
#pragma unroll
        for (int r = 0; r < 8; ++r) s += zs[r][tx];
        atomicAdd(&g_zha[0][b0 + tx], s);
    }
}

// --------------------------------------------------------------------------
// Load one 32-k half (kt in 32-k units) into a 40960-byte half-stage.
// --------------------------------------------------------------------------
__device__ __forceinline__ void load_stage(uint32_t stg, int kt, int tid,
                                           int rowBase, int colBase,
                                           const __nv_bfloat16* Ah, const __nv_bfloat16* Al,
                                           const __nv_bfloat16* Bh, const __nv_bfloat16* Bl) {
#pragma unroll
    for (int i = 0; i < 8; ++i) {
        int ch = i * 256 + tid;
        int tile = ch >> 9;
        int r = (ch >> 2) & 127;
        int c = ch & 3;
        const __nv_bfloat16* base = (tile == 0) ? Ah : (tile == 1) ? Al : (tile == 2) ? Bh : Bl;
        int rb = (tile < 2) ? rowBase : colBase;
        const char* src = (const char*)base + ((size_t)(rb + r) * NN + kt * BKt + c * 8) * 2;
        uint32_t dst = stg + tile * TILEB + r * ROWB + c * 16;
        cp16(dst, src);
    }
}

// Load one full K64 chunk (kt64 in 64-k units) into chunk slot; ONE commit group.
__device__ __forceinline__ void load_chunk64(uint32_t slotBase, int kt64, int tid,
                                             int rowBase, int colBase,
                                             const __nv_bfloat16* Ah, const __nv_bfloat16* Al,
                                             const __nv_bfloat16* Bh, const __nv_bfloat16* Bl) {
    load_stage(slotBase,          kt64 * 2,     tid, rowBase, colBase, Ah, Al, Bh, Bl);
    load_stage(slotBase + STAGEB, kt64 * 2 + 1, tid, rowBase, colBase, Ah, Al, Bh, Bl);
    asm volatile("cp.async.commit_group;" ::: "memory");
}

// --------------------------------------------------------------------------
// Static stream-K fused step kernel; K64 chunks, NSTG=2, single barrier per
// chunk, running slot parity across segments + cross-segment prefetch under
// the epilogue. B fragments loaded with ldsm4 (2 n-octets per instruction).
// grid = nsm, block 256.
// --------------------------------------------------------------------------
__global__ void __launch_bounds__(256, 1) gemm_streamk_kernel(
    int p, int do_mma, int nsm,
    const float* __restrict__ Mv,
    const float* __restrict__ Cc, const float* __restrict__ Amat,
    const float* __restrict__ Bm, const float* __restrict__ Z,
    float* __restrict__ trajh_next,
    float* __restrict__ trajx_cur,
    float* __restrict__ con_cur) {
    extern __shared__ __align__(128) char smem[];
    __shared__ int sflag;
    uint32_t sb = smem_u32(smem);
    float* Cst = (float*)(smem + CST_OFF);
    int tid = threadIdx.x;
    int lane = tid & 31;
    int wid = tid >> 5;
    int q2 = p ^ 1;

    // ---- fused x-update (step t), CTA 0 only ----
    if (blockIdx.x == 0) {
#pragma unroll
        for (int it = 0; it < 2; ++it) {
            int b = tid + it * 256;
            float zh = g_zha[p][b];
            g_zha[p][b] = 0.f;
            float xv0 = g_x[p][b], xv1 = g_x[p][BB + b];
            con_cur[b] = Bm[1] * zh;
            trajx_cur[b] = xv0;
            trajx_cur[BB + b] = xv1;
            g_x[q2][b] = Amat[0] * xv0 + Amat[1] * xv1 + Bm[0] * zh;
            g_x[q2][BB + b] = Amat[2] * xv0 + Amat[3] * xv1 + Bm[1] * zh;
        }
    }
    if (!do_mma) return;

    const __nv_bfloat16* Ah = g_Ahi;
    const __nv_bfloat16* Al = g_Alo;
    const __nv_bfloat16* Bh = g_Bhi[p];
    const __nv_bfloat16* Bl = g_Blo[p];

    int cid = blockIdx.x;
    int c0 = (int)(((long long)cid * TOTC) / nsm);
    int c1 = (int)(((long long)(cid + 1) * TOTC) / nsm);

    int mb = (wid >> 2) * 64;
    int nb = (wid & 3) * 32;
    uint32_t aRow = (uint32_t)(mb + (lane & 15));
    uint32_t aK = (uint32_t)((lane >> 4) * 8);
    // B via ldsm4: lanes 0-7: n-octet0/k0-7; 8-15: n-octet0/k8-15;
    //              16-23: n-octet1/k0-7; 24-31: n-octet1/k8-15.
    uint32_t bRow4 = (uint32_t)(nb + (lane & 7) + ((lane >> 4) & 1) * 8);
    uint32_t bK4 = (uint32_t)(((lane >> 3) & 1) * 8);

    int gg = 0;          // running chunk counter (slot parity persists across segments)
    int prefetched = 0;  // next segment's first chunk already loading into slot gg&1

    while (c0 < c1) {
        int tile = c0 >> 6;               // K64 units: 64 chunks per tile
        int kt0 = c0 & 63;
        int kcnt = min(NCHUNK - kt0, c1 - c0);
        int rowBase = (tile >> 2) * BM;
        int colBase = (tile & 3) * BN;

        float acc[4][4][4];
#pragma unroll
        for (int mi = 0; mi < 4; ++mi)
#pragma unroll
            for (int ni = 0; ni < 4; ++ni)
#pragma unroll
                for (int k = 0; k < 4; ++k) acc[mi][ni][k] = 0.f;

        if (!prefetched)
            load_chunk64(sb + (uint32_t)(gg & 1) * CHUNKB, kt0, tid, rowBase, colBase,
                         Ah, Al, Bh, Bl);

        for (int i = 0; i < kcnt; ++i) {
            asm volatile("cp.async.wait_group 0;" ::: "memory");  // chunk i resident
            __syncthreads();   // all warps drained slot of chunk gg-1

            if (i + 1 < kcnt)
                load_chunk64(sb + (uint32_t)((gg + 1) & 1) * CHUNKB, kt0 + i + 1, tid,
                             rowBase, colBase, Ah, Al, Bh, Bl);

            uint32_t slot = sb + (uint32_t)(gg & 1) * CHUNKB;
#pragma unroll
            for (int ks4 = 0; ks4 < 4; ++ks4) {
                uint32_t stg = slot + (uint32_t)(ks4 >> 1) * STAGEB;
                int ks = (ks4 & 1) * 16;
                uint32_t ah[4][4], al2[4][4], bh2[4][2], bl2[4][2];
#pragma unroll
                for (int mi = 0; mi < 4; ++mi) {
                    uint32_t a = stg + (aRow + mi * 16) * ROWB + (aK + ks) * 2;
                    ldsm4(ah[mi], a);
                    ldsm4(al2[mi], a + TILEB);
                }
#pragma unroll
                for (int nq = 0; nq < 2; ++nq) {
                    uint32_t b = stg + 2 * TILEB + (bRow4 + nq * 16) * ROWB + (bK4 + ks) * 2;
                    ldsm4(&bh2[nq * 2][0], b);          // fills bh2[2nq], bh2[2nq+1]
                    ldsm4(&bl2[nq * 2][0], b + TILEB);
                }
#pragma unroll
                for (int mi = 0; mi < 4; ++mi)
#pragma unroll
                    for (int ni = 0; ni < 4; ++ni) {
                        mma_bf16(acc[mi][ni], ah[mi], bh2[ni]);
                        mma_bf16(acc[mi][ni], ah[mi], bl2[ni]);
                        mma_bf16(acc[mi][ni], al2[mi], bh2[ni]);
                    }
            }
            ++gg;
        }

        // ---- cross-segment prefetch into slot gg&1 (drained: all warps passed
        //      the last iteration's barrier after consuming chunk gg-2) ----
        int nc0 = c0 + kcnt;
        if (nc0 < c1) {
            int nTile = nc0 >> 6;
            load_chunk64(sb + (uint32_t)(gg & 1) * CHUNKB, nc0 & 63, tid,
                         (nTile >> 2) * BM, (nTile & 3) * BN, Ah, Al, Bh, Bl);
            prefetched = 1;
        } else {
            prefetched = 0;
        }

        // ---- pass 1: frags -> Cst [n][132] (separate region) ----
#pragma unroll
        for (int mi = 0; mi < 4; ++mi)
#pragma unroll
            for (int ni = 0; ni < 4; ++ni) {
                int m = mb + mi * 16 + (lane >> 2);
                int n = nb + ni * 8 + (lane & 3) * 2;
                Cst[n * 132 + m] = acc[mi][ni][0];
                Cst[(n + 1) * 132 + m] = acc[mi][ni][1];
                Cst[n * 132 + m + 8] = acc[mi][ni][2];
                Cst[(n + 1) * 132 + m + 8] = acc[mi][ni][3];
            }
        __syncthreads();

        // ---- store my partial to my slot (plain, coalesced) ----
        int firstOwner = (int)((((long long)(tile << 6) + 1) * nsm - 1) / TOTC);
        int lastOwner  = (int)((((long long)(tile << 6) + NCHUNK) * nsm - 1) / TOTC);
        int slot = cid - firstOwner;
        int nslots = lastOwner - firstOwner + 1;
        float* part = g_Cpart + ((size_t)(tile * 3 + slot) << 14);
#pragma unroll
        for (int it = 0; it < 16; ++it) {
            int lin = it * 1024 + tid * 4;
            int n = lin >> 7, m = lin & 127;
            *(float4*)&part[lin] = *(float4*)&Cst[n * 132 + m];
        }
        __threadfence();
        __syncthreads();
        if (tid == 0) {
            int old = atomicAdd(&g_cnt[tile], kcnt);
            sflag = (old + kcnt == NCHUNK) ? 1 : 0;
        }
        __syncthreads();

        if (sflag) {
            __threadfence();   // acquire: other slots' data visible
            for (int s = 0; s < nslots; ++s) {
                if (s == slot) continue;
                const float* op = g_Cpart + ((size_t)(tile * 3 + s) << 14);
#pragma unroll
                for (int it = 0; it < 16; ++it) {
                    int lin = it * 1024 + tid * 4;
                    int n = lin >> 7, m = lin & 127;
                    float4 a = *(float4*)&Cst[n * 132 + m];
                    float4 b = *(const float4*)&op[lin];
                    a.x += b.x; a.y += b.y; a.z += b.z; a.w += b.w;
                    *(float4*)&Cst[n * 132 + m] = a;
                }
            }
            __syncthreads();

            // ---- pass 2 (n-major): v = C + DT*M*e; Bhi/Blo out, zh partial
            float CA0 = Cc[0] * Amat[0] + Cc[1] * Amat[2];
            float CA1 = Cc[0] * Amat[1] + Cc[1] * Amat[3];
            {
                int n = tid >> 1;
                int m0 = (tid & 1) * 64;
                float e = CA0 * g_x[p][colBase + n] + CA1 * g_x[p][BB + colBase + n];
                __nv_bfloat16* __restrict__ Bhn = g_Bhi[q2];
                __nv_bfloat16* __restrict__ Bln = g_Blo[q2];
                size_t obase = (size_t)(colBase + n) * NN + rowBase;
                float zp = 0.f;
#pragma unroll
                for (int q = 0; q < 16; ++q) {
                    int m = m0 + q * 4;
                    float4 c = *(float4*)&Cst[n * 132 + m];
                    float4 mv4 = *(const float4*)&Mv[rowBase + m];
                    float4 z4 = *(const float4*)&Z[rowBase + m];
                    float4 v;
                    v.x = c.x + DTc * mv4.x * e;
                    v.y = c.y + DTc * mv4.y * e;
                    v.z = c.z + DTc * mv4.z * e;
                    v.w = c.w + DTc * mv4.w * e;
                    *(float4*)&Cst[n * 132 + m] = v;
                    zp += z4.x * v.x + z4.y * v.y + z4.z * v.z + z4.w * v.w;
                    union { __nv_bfloat16 h[4]; uint2 u; } ph, pl;
                    const float* vp = &v.x;
#pragma unroll
                    for (int j = 0; j < 4; ++j) {
                        __nv_bfloat16 hi = __float2bfloat16(vp[j]);
                        ph.h[j] = hi;
                        pl.h[j] = __float2bfloat16(vp[j] - __bfloat162float(hi));
                    }
                    *(uint2*)&Bhn[obase + m] = ph.u;
                    *(uint2*)&Bln[obase + m] = pl.u;
                }
                zp += __shfl_xor_sync(0xFFFFFFFFu, zp, 1);
                if ((tid & 1) == 0)
                    atomicAdd(&g_zha[q2][colBase + n], zp);
            }
            __syncthreads();

            // ---- pass 3 (m-major): traj_{t+1} h-block ----
            {
                int m = tid >> 1;
                int n0 = (tid & 1) * 64;
                size_t tb = (size_t)(rowBase + m) * BB + colBase + n0;
#pragma unroll
                for (int q = 0; q < 16; ++q) {
                    float4 v;
                    v.x = Cst[(n0 + q * 4 + 0) * 132 + m];
                    v.y = Cst[(n0 + q * 4 + 1) * 132 + m];
                    v.z = Cst[(n0 + q * 4 + 2) * 132 + m];
                    v.w = Cst[(n0 + q * 4 + 3) * 132 + m];
                    *(float4*)&trajh_next[tb + q * 4] = v;
                }
            }
            if (tid == 0) atomicExch(&g_cnt[tile], 0);   // restore for next step
        }
        __syncthreads();   // Cst reuse safe before next segment
        c0 = nc0;
    }
}

// --------------------------------------------------------------------------
extern "C" void kernel_launch(void* const* d_in, const int* in_sizes, int n_in,
                              void* d_out, int out_size) {
    const float* x0 = (const float*)d_in[0];
    const float* x1 = (const float*)d_in[1];
    const float* h0 = (const float*)d_in[2];
    const float* A  = (const float*)d_in[3];
    const float* Bm = (const float*)d_in[4];
    const float* C  = (const float*)d_in[5];
    const float* Mv = (const float*)d_in[6];
    const float* Z  = (const float*)d_in[7];
    const float* U  = (const float*)d_in[8];
    const float* V  = (const float*)d_in[9];
    const float* W  = (const float*)d_in[10];

    long long per_step_full = (long long)BB * (NN + 2 + 1);
    int steps = (int)((long long)out_size / per_step_full);
    if ((long long)steps * per_step_full != (long long)out_size)
        steps = (int)((long long)out_size / ((long long)BB * (NN + 2)));

    float* out  = (float*)d_out;
    float* traj = out;
    float* con  = out + (size_t)steps * (NN + 2) * BB;

    int nsm = 0;
    cudaDeviceGetAttribute(&nsm, cudaDevAttrMultiProcessorCount, 0);
    if (nsm < 8 || nsm > 512) nsm = 148;

    cudaFuncSetAttribute(gemm_streamk_kernel,
                         cudaFuncAttributeMaxDynamicSharedMemorySize, SMEM_BYTES);

    build_split_kernel<<<dim3(NN / 4 / 256, NN), 256>>>(W, U, V, Mv, Z, C, Bm);
    init_all_kernel<<<dim3(NN / 32, BB / 32), dim3(32, 8)>>>(h0, x0, x1, Z, traj + 2 * BB);

    for (int t = 0; t < steps; ++t) {
        int p = t & 1;
        int do_mma = (t < steps - 1);
        float* traj_t = traj + (size_t)t * (NN + 2) * BB;
        float* trajh_next = traj + (size_t)(t + 1) * (NN + 2) * BB + 2 * BB;
        if (!do_mma) trajh_next = traj_t + 2 * BB;   // unused, keep in-bounds
        gemm_streamk_kernel<<<nsm, 256, SMEM_BYTES>>>(
            p, do_mma, nsm, Mv, C, A, Bm, Z,
            trajh_next, traj_t, con + (size_t)t * BB);
    }
}

// round 16
// speedup vs baseline: 1.5605x; 1.0065x over previous
#include <cuda_runtime.h>
#include <cuda_bf16.h>
#include <cstdint>

#define NN 4096
#define BB 512
#define DTc 0.1f

// GEMM tiling (mma.sync bf16)
#define BM 128
#define BN 128
#define BKt 32                       // 32-k granularity of load_stage / smem layout
#define NCHUNK 64                    // K64-chunks per tile (4096/64)
#define NTILES 128                   // 32 M x 4 N
#define TOTC (NTILES * NCHUNK)       // 8192
#define ROWB 80
#define TILEB (128 * ROWB)
#define STAGEB (4 * TILEB)           // 40960 (one 32-k half)
#define CHUNKB (2 * STAGEB)          // 81920 (one K64 chunk slot)
#define NSTG 2
#define CST_OFF (NSTG * CHUNKB)      // 163840
#define SMEM_BYTES (CST_OFF + 128 * 132 * 4)   // 231424

// --------------------------------------------------------------------------
__device__ __align__(256) __nv_bfloat16 g_Ahi[(size_t)NN * NN];    // 32 MB
__device__ __align__(256) __nv_bfloat16 g_Alo[(size_t)NN * NN];    // 32 MB
__device__ __align__(256) __nv_bfloat16 g_Bhi[2][(size_t)BB * NN]; // 2x4 MB
__device__ __align__(256) __nv_bfloat16 g_Blo[2][(size_t)BB * NN]; // 2x4 MB
__device__ __align__(256) float g_Cpart[(size_t)NTILES * 3 * 128 * 128]; // 25.2 MB
__device__ int g_cnt[NTILES];        // zero-init; kernel restores zeros
__device__ float g_x[2][2 * BB];
__device__ float g_zha[2][BB];

// --------------------------------------------------------------------------
__device__ __forceinline__ uint32_t smem_u32(const void* p) {
    return (uint32_t)__cvta_generic_to_shared((void*)p);
}
__device__ __forceinline__ void cp16(uint32_t dst, const void* src) {
    asm volatile("cp.async.cg.shared.global [%0], [%1], 16;" :: "r"(dst), "l"(src) : "memory");
}
__device__ __forceinline__ void ldsm4(uint32_t* r, uint32_t a) {
    asm volatile("ldmatrix.sync.aligned.m8n8.x4.shared.b16 {%0,%1,%2,%3}, [%4];"
                 : "=r"(r[0]), "=r"(r[1]), "=r"(r[2]), "=r"(r[3]) : "r"(a));
}
__device__ __forceinline__ void mma_bf16(float* d, const uint32_t* a, const uint32_t* b) {
    asm("mma.sync.aligned.m16n8k16.row.col.f32.bf16.bf16.f32 "
        "{%0,%1,%2,%3}, {%4,%5,%6,%7}, {%8,%9}, {%0,%1,%2,%3};"
        : "+f"(d[0]), "+f"(d[1]), "+f"(d[2]), "+f"(d[3])
        : "r"(a[0]), "r"(a[1]), "r"(a[2]), "r"(a[3]), "r"(b[0]), "r"(b[1]));
}

// --------------------------------------------------------------------------
// Build A_hi/A_lo (bf16 split of P22); zero zh accumulators + counters.
// --------------------------------------------------------------------------
__global__ void build_split_kernel(const float* __restrict__ W,
                                   const float* __restrict__ U,
                                   const float* __restrict__ V,
                                   const float* __restrict__ Mv,
                                   const float* __restrict__ Z,
                                   const float* __restrict__ Cc,
                                   const float* __restrict__ Bm) {
    if (blockIdx.x == 0 && blockIdx.y == 0) {
        int tIdx = threadIdx.x;
        g_zha[0][tIdx] = 0.f;       g_zha[1][tIdx] = 0.f;
        g_zha[0][tIdx + 256] = 0.f; g_zha[1][tIdx + 256] = 0.f;
        if (tIdx < NTILES) g_cnt[tIdx] = 0;
    }
    int i = blockIdx.y;
    int j = (blockIdx.x * blockDim.x + threadIdx.x) * 4;
    float cb = Cc[0] * Bm[0] + Cc[1] * Bm[1];
    float mi = Mv[i];
    float u0 = U[i * 4 + 0], u1 = U[i * 4 + 1], u2 = U[i * 4 + 2], u3 = U[i * 4 + 3];
    float4 w = *(const float4*)(W + (size_t)i * NN + j);
    const float* wp = &w.x;
    union { __nv_bfloat16 h[4]; uint2 u; } ph, pl;
#pragma unroll
    for (int jj = 0; jj < 4; ++jj) {
        int jc = j + jj;
        float4 vv = *(const float4*)(V + (size_t)jc * 4);
        float uv = u0 * vv.x + u1 * vv.y + u2 * vv.z + u3 * vv.w;
        float val = DTc * (wp[jj] + uv) + cb * mi * Z[jc];
        if (jc == i) val += 1.0f - DTc;
        __nv_bfloat16 hi = __float2bfloat16(val);
        ph.h[jj] = hi;
        pl.h[jj] = __float2bfloat16(val - __bfloat162float(hi));
    }
    *(uint2*)(g_Ahi + (size_t)i * NN + j) = ph.u;
    *(uint2*)(g_Alo + (size_t)i * NN + j) = pl.u;
}

// --------------------------------------------------------------------------
// init_all: h0 -> traj_0 h-block + transposed bf16 split + zh0 + x init
// --------------------------------------------------------------------------
__global__ void init_all_kernel(const float* __restrict__ h0,
                                const float* __restrict__ x0,
                                const float* __restrict__ x1,
                                const float* __restrict__ Z,
                                float* __restrict__ traj0h) {
    __shared__ float t[32][33];
    __shared__ float zs[8][33];
    int m0 = blockIdx.x * 32, b0 = blockIdx.y * 32;
    int tx = threadIdx.x, ty = threadIdx.y;
    if (blockIdx.x == 0 && blockIdx.y == 0) {
        int tid = ty * 32 + tx;
#pragma unroll
        for (int it = 0; it < 2; ++it) {
            int b = tid + it * 256;
            g_x[0][b] = x0[b];
            g_x[0][BB + b] = x1[b];
        }
    }
#pragma unroll
    for (int j = 0; j < 32; j += 8) {
        size_t a = (size_t)(m0 + ty + j) * BB + b0 + tx;
        float v = h0[a];
        traj0h[a] = v;
        t[ty + j][tx] = v;
    }
    __syncthreads();
    {
        float s = 0.f;
#pragma unroll
        for (int i = 0; i < 4; ++i) {
            int r = ty * 4 + i;
            s = fmaf(Z[m0 + r], t[r][tx], s);
        }
        zs[ty][tx] = s;
    }
#pragma unroll
    for (int j = 0; j < 32; j += 8) {
        float v = t[tx][ty + j];
        size_t o = (size_t)(b0 + ty + j) * NN + m0 + tx;
        __nv_bfloat16 hi = __float2bfloat16(v);
        g_Bhi[0][o] = hi;
        g_Blo[0][o] = __float2bfloat16(v - __bfloat162float(hi));
    }
    __syncthreads();
    if (ty == 0) {
        float s = 0.f;
#pragma unroll
        for (int r = 0; r < 8; ++r) s += zs[r][tx];
        atomicAdd(&g_zha[0][b0 + tx], s);
    }
}

// --------------------------------------------------------------------------
// Load one 32-k half (kt in 32-k units) into a 40960-byte half-stage.
// --------------------------------------------------------------------------
__device__ __forceinline__ void load_stage(uint32_t stg, int kt, int tid,
                                           int rowBase, int colBase,
                                           const __nv_bfloat16* Ah, const __nv_bfloat16* Al,
                                           const __nv_bfloat16* Bh, const __nv_bfloat16* Bl) {
#pragma unroll
    for (int i = 0; i < 8; ++i) {
        int ch = i * 256 + tid;
        int tile = ch >> 9;
        int r = (ch >> 2) & 127;
        int c = ch & 3;
        const __nv_bfloat16* base = (tile == 0) ? Ah : (tile == 1) ? Al : (tile == 2) ? Bh : Bl;
        int rb = (tile < 2) ? rowBase : colBase;
        const char* src = (const char*)base + ((size_t)(rb + r) * NN + kt * BKt + c * 8) * 2;
        uint32_t dst = stg + tile * TILEB + r * ROWB + c * 16;
        cp16(dst, src);
    }
}

// Load one full K64 chunk (kt64 in 64-k units) into chunk slot; ONE commit group.
__device__ __forceinline__ void load_chunk64(uint32_t slotBase, int kt64, int tid,
                                             int rowBase, int colBase,
                                             const __nv_bfloat16* Ah, const __nv_bfloat16* Al,
                                             const __nv_bfloat16* Bh, const __nv_bfloat16* Bl) {
    load_stage(slotBase,          kt64 * 2,     tid, rowBase, colBase, Ah, Al, Bh, Bl);
    load_stage(slotBase + STAGEB, kt64 * 2 + 1, tid, rowBase, colBase, Ah, Al, Bh, Bl);
    asm volatile("cp.async.commit_group;" ::: "memory");
}

// --------------------------------------------------------------------------
// Static stream-K fused step kernel; K64 chunks, NSTG=2, single barrier per
// chunk, running slot parity, cross-segment prefetch under the epilogue.
// Partials exchanged in FRAGMENT layout (register<->global direct, no smem
// detour); only the finisher touches Cst. x-update runs at CTA0's TAIL.
// grid = nsm, block 256.
// --------------------------------------------------------------------------
__global__ void __launch_bounds__(256, 1) gemm_streamk_kernel(
    int p, int do_mma, int nsm,
    const float* __restrict__ Mv,
    const float* __restrict__ Cc, const float* __restrict__ Amat,
    const float* __restrict__ Bm, const float* __restrict__ Z,
    float* __restrict__ trajh_next,
    float* __restrict__ trajx_cur,
    float* __restrict__ con_cur) {
    extern __shared__ __align__(128) char smem[];
    __shared__ int sflag;
    uint32_t sb = smem_u32(smem);
    float* Cst = (float*)(smem + CST_OFF);
    int tid = threadIdx.x;
    int lane = tid & 31;
    int wid = tid >> 5;
    int q2 = p ^ 1;

    if (do_mma) {
        const __nv_bfloat16* Ah = g_Ahi;
        const __nv_bfloat16* Al = g_Alo;
        const __nv_bfloat16* Bh = g_Bhi[p];
        const __nv_bfloat16* Bl = g_Blo[p];

        int cid = blockIdx.x;
        int c0 = (int)(((long long)cid * TOTC) / nsm);
        int c1 = (int)(((long long)(cid + 1) * TOTC) / nsm);

        int mb = (wid >> 2) * 64;
        int nb = (wid & 3) * 32;
        uint32_t aRow = (uint32_t)(mb + (lane & 15));
        uint32_t aK = (uint32_t)((lane >> 4) * 8);
        // B via ldsm4: lanes 0-7: n-octet0/k0-7; 8-15: n-octet0/k8-15;
        //              16-23: n-octet1/k0-7; 24-31: n-octet1/k8-15.
        uint32_t bRow4 = (uint32_t)(nb + (lane & 7) + ((lane >> 4) & 1) * 8);
        uint32_t bK4 = (uint32_t)(((lane >> 3) & 1) * 8);

        int gg = 0;          // running chunk counter (slot parity across segments)
        int prefetched = 0;

        while (c0 < c1) {
            int tile = c0 >> 6;
            int kt0 = c0 & 63;
            int kcnt = min(NCHUNK - kt0, c1 - c0);
            int rowBase = (tile >> 2) * BM;
            int colBase = (tile & 3) * BN;

            float acc[4][4][4];
#pragma unroll
            for (int mi = 0; mi < 4; ++mi)
#pragma unroll
                for (int ni = 0; ni < 4; ++ni)
#pragma unroll
                    for (int k = 0; k < 4; ++k) acc[mi][ni][k] = 0.f;

            if (!prefetched)
                load_chunk64(sb + (uint32_t)(gg & 1) * CHUNKB, kt0, tid, rowBase, colBase,
                             Ah, Al, Bh, Bl);

            for (int i = 0; i < kcnt; ++i) {
                asm volatile("cp.async.wait_group 0;" ::: "memory");
                __syncthreads();

                if (i + 1 < kcnt)
                    load_chunk64(sb + (uint32_t)((gg + 1) & 1) * CHUNKB, kt0 + i + 1, tid,
                                 rowBase, colBase, Ah, Al, Bh, Bl);

                uint32_t slot = sb + (uint32_t)(gg & 1) * CHUNKB;
#pragma unroll
                for (int ks4 = 0; ks4 < 4; ++ks4) {
                    uint32_t stg = slot + (uint32_t)(ks4 >> 1) * STAGEB;
                    int ks = (ks4 & 1) * 16;
                    uint32_t ah[4][4], al2[4][4], bh2[4][2], bl2[4][2];
#pragma unroll
                    for (int mi = 0; mi < 4; ++mi) {
                        uint32_t a = stg + (aRow + mi * 16) * ROWB + (aK + ks) * 2;
                        ldsm4(ah[mi], a);
                        ldsm4(al2[mi], a + TILEB);
                    }
#pragma unroll
                    for (int nq = 0; nq < 2; ++nq) {
                        uint32_t b = stg + 2 * TILEB + (bRow4 + nq * 16) * ROWB + (bK4 + ks) * 2;
                        ldsm4(&bh2[nq * 2][0], b);
                        ldsm4(&bl2[nq * 2][0], b + TILEB);
                    }
#pragma unroll
                    for (int mi = 0; mi < 4; ++mi)
#pragma unroll
                        for (int ni = 0; ni < 4; ++ni) {
                            mma_bf16(acc[mi][ni], ah[mi], bh2[ni]);
                            mma_bf16(acc[mi][ni], ah[mi], bl2[ni]);
                            mma_bf16(acc[mi][ni], al2[mi], bh2[ni]);
                        }
                }
                ++gg;
            }

            // ---- cross-segment prefetch into slot gg&1 (provably drained) ----
            int nc0 = c0 + kcnt;
            if (nc0 < c1) {
                int nTile = nc0 >> 6;
                load_chunk64(sb + (uint32_t)(gg & 1) * CHUNKB, nc0 & 63, tid,
                             (nTile >> 2) * BM, (nTile & 3) * BN, Ah, Al, Bh, Bl);
                prefetched = 1;
            } else {
                prefetched = 0;
            }

            // ---- partial exchange in FRAGMENT layout (no smem detour) ----
            int firstOwner = (int)((((long long)(tile << 6) + 1) * nsm - 1) / TOTC);
            int lastOwner  = (int)((((long long)(tile << 6) + NCHUNK) * nsm - 1) / TOTC);
            int slot = cid - firstOwner;
            int nslots = lastOwner - firstOwner + 1;
            float* part = g_Cpart + ((size_t)(tile * 3 + slot) << 14);
#pragma unroll
            for (int q = 0; q < 16; ++q) {
                float4 v;
                v.x = acc[q >> 2][q & 3][0];
                v.y = acc[q >> 2][q & 3][1];
                v.z = acc[q >> 2][q & 3][2];
                v.w = acc[q >> 2][q & 3][3];
                *(float4*)&part[(q * 256 + tid) * 4] = v;
            }
            __threadfence();
            __syncthreads();
            if (tid == 0) {
                int old = atomicAdd(&g_cnt[tile], kcnt);
                sflag = (old + kcnt == NCHUNK) ? 1 : 0;
            }
            __syncthreads();

            if (sflag) {
                __threadfence();   // acquire: other slots' data visible
                for (int s = 0; s < nslots; ++s) {
                    if (s == slot) continue;
                    const float* op = g_Cpart + ((size_t)(tile * 3 + s) << 14);
#pragma unroll
                    for (int q = 0; q < 16; ++q) {
                        float4 b = *(const float4*)&op[(q * 256 + tid) * 4];
                        acc[q >> 2][q & 3][0] += b.x;
                        acc[q >> 2][q & 3][1] += b.y;
                        acc[q >> 2][q & 3][2] += b.z;
                        acc[q >> 2][q & 3][3] += b.w;
                    }
                }

                // ---- pass 1 (finisher only): full acc -> Cst [n][132] ----
#pragma unroll
                for (int mi = 0; mi < 4; ++mi)
#pragma unroll
                    for (int ni = 0; ni < 4; ++ni) {
                        int m = mb + mi * 16 + (lane >> 2);
                        int n = nb + ni * 8 + (lane & 3) * 2;
                        Cst[n * 132 + m] = acc[mi][ni][0];
                        Cst[(n + 1) * 132 + m] = acc[mi][ni][1];
                        Cst[n * 132 + m + 8] = acc[mi][ni][2];
                        Cst[(n + 1) * 132 + m + 8] = acc[mi][ni][3];
                    }
                __syncthreads();

                // ---- pass 2 (n-major): v = C + DT*M*e; Bhi/Blo out, zh ----
                float CA0 = Cc[0] * Amat[0] + Cc[1] * Amat[2];
                float CA1 = Cc[0] * Amat[1] + Cc[1] * Amat[3];
                {
                    int n = tid >> 1;
                    int m0 = (tid & 1) * 64;
                    float e = CA0 * g_x[p][colBase + n] + CA1 * g_x[p][BB + colBase + n];
                    __nv_bfloat16* __restrict__ Bhn = g_Bhi[q2];
                    __nv_bfloat16* __restrict__ Bln = g_Blo[q2];
                    size_t obase = (size_t)(colBase + n) * NN + rowBase;
                    float zp = 0.f;
#pragma unroll
                    for (int q = 0; q < 16; ++q) {
                        int m = m0 + q * 4;
                        float4 c = *(float4*)&Cst[n * 132 + m];
                        float4 mv4 = *(const float4*)&Mv[rowBase + m];
                        float4 z4 = *(const float4*)&Z[rowBase + m];
                        float4 v;
                        v.x = c.x + DTc * mv4.x * e;
                        v.y = c.y + DTc * mv4.y * e;
                        v.z = c.z + DTc * mv4.z * e;
                        v.w = c.w + DTc * mv4.w * e;
                        *(float4*)&Cst[n * 132 + m] = v;
                        zp += z4.x * v.x + z4.y * v.y + z4.z * v.z + z4.w * v.w;
                        union { __nv_bfloat16 h[4]; uint2 u; } ph, pl;
                        const float* vp = &v.x;
#pragma unroll
                        for (int j = 0; j < 4; ++j) {
                            __nv_bfloat16 hi = __float2bfloat16(vp[j]);
                            ph.h[j] = hi;
                            pl.h[j] = __float2bfloat16(vp[j] - __bfloat162float(hi));
                        }
                        *(uint2*)&Bhn[obase + m] = ph.u;
                        *(uint2*)&Bln[obase + m] = pl.u;
                    }
                    zp += __shfl_xor_sync(0xFFFFFFFFu, zp, 1);
                    if ((tid & 1) == 0)
                        atomicAdd(&g_zha[q2][colBase + n], zp);
                }
                __syncthreads();

                // ---- pass 3 (m-major): traj_{t+1} h-block ----
                {
                    int m = tid >> 1;
                    int n0 = (tid & 1) * 64;
                    size_t tb = (size_t)(rowBase + m) * BB + colBase + n0;
#pragma unroll
                    for (int q = 0; q < 16; ++q) {
                        float4 v;
                        v.x = Cst[(n0 + q * 4 + 0) * 132 + m];
                        v.y = Cst[(n0 + q * 4 + 1) * 132 + m];
                        v.z = Cst[(n0 + q * 4 + 2) * 132 + m];
                        v.w = Cst[(n0 + q * 4 + 3) * 132 + m];
                        *(float4*)&trajh_next[tb + q * 4] = v;
                    }
                }
                if (tid == 0) atomicExch(&g_cnt[tile], 0);
            }
            __syncthreads();   // sflag/Cst reuse safe before next segment
            c0 = nc0;
        }
    }

    // ---- fused x-update (step t) at CTA0's TAIL (no intra-launch consumer) ----
    if (blockIdx.x == 0) {
#pragma unroll
        for (int it = 0; it < 2; ++it) {
            int b = tid + it * 256;
            float zh = g_zha[p][b];
            g_zha[p][b] = 0.f;
            float xv0 = g_x[p][b], xv1 = g_x[p][BB + b];
            con_cur[b] = Bm[1] * zh;
            trajx_cur[b] = xv0;
            trajx_cur[BB + b] = xv1;
            g_x[q2][b] = Amat[0] * xv0 + Amat[1] * xv1 + Bm[0] * zh;
            g_x[q2][BB + b] = Amat[2] * xv0 + Amat[3] * xv1 + Bm[1] * zh;
        }
    }
}

// --------------------------------------------------------------------------
extern "C" void kernel_launch(void* const* d_in, const int* in_sizes, int n_in,
                              void* d_out, int out_size) {
    const float* x0 = (const float*)d_in[0];
    const float* x1 = (const float*)d_in[1];
    const float* h0 = (const float*)d_in[2];
    const float* A  = (const float*)d_in[3];
    const float* Bm = (const float*)d_in[4];
    const float* C  = (const float*)d_in[5];
    const float* Mv = (const float*)d_in[6];
    const float* Z  = (const float*)d_in[7];
    const float* U  = (const float*)d_in[8];
    const float* V  = (const float*)d_in[9];
    const float* W  = (const float*)d_in[10];

    long long per_step_full = (long long)BB * (NN + 2 + 1);
    int steps = (int)((long long)out_size / per_step_full);
    if ((long long)steps * per_step_full != (long long)out_size)
        steps = (int)((long long)out_size / ((long long)BB * (NN + 2)));

    float* out  = (float*)d_out;
    float* traj = out;
    float* con  = out + (size_t)steps * (NN + 2) * BB;

    int nsm = 0;
    cudaDeviceGetAttribute(&nsm, cudaDevAttrMultiProcessorCount, 0);
    if (nsm < 8 || nsm > 512) nsm = 148;

    cudaFuncSetAttribute(gemm_streamk_kernel,
                         cudaFuncAttributeMaxDynamicSharedMemorySize, SMEM_BYTES);

    build_split_kernel<<<dim3(NN / 4 / 256, NN), 256>>>(W, U, V, Mv, Z, C, Bm);
    init_all_kernel<<<dim3(NN / 32, BB / 32), dim3(32, 8)>>>(h0, x0, x1, Z, traj + 2 * BB);

    for (int t = 0; t < steps; ++t) {
        int p = t & 1;
        int do_mma = (t < steps - 1);
        float* traj_t = traj + (size_t)t * (NN + 2) * BB;
        float* trajh_next = traj + (size_t)(t + 1) * (NN + 2) * BB + 2 * BB;
        if (!do_mma) trajh_next = traj_t + 2 * BB;   // unused, keep in-bounds
        gemm_streamk_kernel<<<nsm, 256, SMEM_BYTES>>>(
            p, do_mma, nsm, Mv, C, A, Bm, Z,
            trajh_next, traj_t, con + (size_t)t * BB);
    }
}